// round 6
// baseline (speedup 1.0000x reference)
#include <cuda_runtime.h>
#include <cuda_bf16.h>
#include <math.h>
#include <stdint.h>

#define BB 256
#define HH 512
#define NNODES 128
#define NCTA 128

// ============================================================================
// PTX helpers (sm_80+ only — tcgen05 is sm_103a-gated, harness emits compute_103)
// ============================================================================
__device__ __forceinline__ uint32_t smem_u32(const void* p) {
    uint32_t a;
    asm("{ .reg .u64 t; cvta.to.shared.u64 t, %1; cvt.u32.u64 %0, t; }" : "=r"(a) : "l"(p));
    return a;
}
__device__ __forceinline__ void cp16(uint32_t saddr, const void* g) {
    asm volatile("cp.async.cg.shared.global [%0], [%1], 16;" :: "r"(saddr), "l"(g));
}
#define CP_COMMIT() asm volatile("cp.async.commit_group;" ::: "memory")
#define LDSM4(r, a) asm volatile("ldmatrix.sync.aligned.m8n8.x4.shared.b16 {%0,%1,%2,%3}, [%4];" \
    : "=r"((r)[0]), "=r"((r)[1]), "=r"((r)[2]), "=r"((r)[3]) : "r"(a))

__device__ __forceinline__ void mma16816(float* c, const uint32_t* a, const uint32_t* b) {
    asm volatile("mma.sync.aligned.m16n8k16.row.col.f32.bf16.bf16.f32 "
                 "{%0,%1,%2,%3}, {%4,%5,%6,%7}, {%8,%9}, {%0,%1,%2,%3};"
                 : "+f"(c[0]), "+f"(c[1]), "+f"(c[2]), "+f"(c[3])
                 : "r"(a[0]), "r"(a[1]), "r"(a[2]), "r"(a[3]), "r"(b[0]), "r"(b[1]));
}

// ============================================================================
// Device globals
// ============================================================================
__device__ __align__(16) __nv_bfloat16 g_W0h[2048 * 640],  g_W0l[2048 * 640];
__device__ __align__(16) __nv_bfloat16 g_W1h[2048 * 1024], g_W1l[2048 * 1024];
__device__ __align__(16) float g_W1ft[512 * 512], g_W2ft[512 * 1024];
__device__ __align__(16) float g_bg0[2048], g_bg1[2048];
__device__ __align__(16) __nv_bfloat16 g_H0h[2][BB * HH], g_H0l[2][BB * HH];
__device__ __align__(16) __nv_bfloat16 g_H1h[2][BB * HH], g_H1l[2][BB * HH];
__device__ __align__(16) __nv_bfloat16 g_DECh[2][BB * 128], g_DECl[2][BB * 128];
__device__ __align__(16) float g_h1f[BB * HH];
__device__ __align__(16) float g_t[BB * 512], g_hx[BB * 1024];
__device__ unsigned char g_used[BB * NNODES];
// per-mt-group flag barriers (monotonic across graph replays)
__device__ __align__(64) unsigned g_flags[8][16];

__device__ __forceinline__ void bsplit(float x, __nv_bfloat16& h, __nv_bfloat16& l) {
    h = __float2bfloat16(x);
    l = __float2bfloat16(x - __bfloat162float(h));
}
__device__ __forceinline__ float sigf(float v) { return 1.f / (1.f + expf(-v)); }

// 16-CTA group barrier: write own flag (release), poll group's 16 flags (acquire)
__device__ __forceinline__ void group_sync(unsigned* gf, int nt, unsigned target) {
    __syncthreads();
    if (threadIdx.x == 0)
        asm volatile("st.release.gpu.global.u32 [%0], %1;" :: "l"(gf + nt), "r"(target) : "memory");
    if (threadIdx.x < 16) {
        unsigned v;
        do {
            asm volatile("ld.acquire.gpu.global.u32 %0, [%1];"
                         : "=r"(v) : "l"(gf + threadIdx.x) : "memory");
        } while (v < target);
    }
    __syncthreads();
}

// ============================================================================
// Weight prep. Packed cols: pc = G*16 + (gate>>1)*8 + u*2 + (gate&1),
// unit h = G*4 + u, original row n = gate*512 + h. Thread's 4 acc fragments
// then hold exactly (i,f,g,o) of one hidden unit.
// ============================================================================
__global__ void prep_weights(const float* __restrict__ Wih0, const float* __restrict__ Whh0,
                             const float* __restrict__ bih0, const float* __restrict__ bhh0,
                             const float* __restrict__ Wih1, const float* __restrict__ Whh1,
                             const float* __restrict__ bih1, const float* __restrict__ bhh1,
                             const float* __restrict__ W1,   const float* __restrict__ W2)
{
    const long S0 = 2048L * 640;
    const long S1 = S0 + 2048L * 1024;
    const long S2 = S1 + 512L * 512;
    const long S3 = S2 + 512L * 1024;
    const long S4 = S3 + 2048;
    const long S5 = S4 + 2048;
    long stride = (long)gridDim.x * blockDim.x;
    for (long i = (long)blockIdx.x * blockDim.x + threadIdx.x; i < S5; i += stride) {
        if (i < S0) {
            long r = i; int pc = (int)(r / 640), k = (int)(r % 640);
            int r16 = pc & 15;
            int gate = ((r16 >> 3) << 1) | (r16 & 1);
            int n = gate * 512 + (pc >> 4) * 4 + ((r16 >> 1) & 3);
            float w = (k < 128) ? Wih0[(long)n * 128 + k] : Whh0[(long)n * 512 + (k - 128)];
            bsplit(w, g_W0h[r], g_W0l[r]);
        } else if (i < S1) {
            long r = i - S0; int pc = (int)(r / 1024), k = (int)(r % 1024);
            int r16 = pc & 15;
            int gate = ((r16 >> 3) << 1) | (r16 & 1);
            int n = gate * 512 + (pc >> 4) * 4 + ((r16 >> 1) & 3);
            float w = (k < 512) ? Wih1[(long)n * 512 + k] : Whh1[(long)n * 512 + (k - 512)];
            bsplit(w, g_W1h[r], g_W1l[r]);
        } else if (i < S2) {
            long r = i - S1; int k = (int)(r / 512), j = (int)(r % 512);
            g_W1ft[r] = W1[(long)j * 512 + k];
        } else if (i < S3) {
            long r = i - S2; int k = (int)(r / 1024), j = (int)(r % 1024);
            g_W2ft[r] = W2[(long)j * 512 + k];
        } else if (i < S4) {
            int pc = (int)(i - S3);
            int r16 = pc & 15;
            int gate = ((r16 >> 3) << 1) | (r16 & 1);
            int n = gate * 512 + (pc >> 4) * 4 + ((r16 >> 1) & 3);
            g_bg0[pc] = bih0[n] + bhh0[n];
        } else {
            int pc = (int)(i - S4);
            int r16 = pc & 15;
            int gate = ((r16 >> 3) << 1) | (r16 & 1);
            int n = gate * 512 + (pc >> 4) * 4 + ((r16 >> 1) & 3);
            g_bg1[pc] = bih1[n] + bhh1[n];
        }
    }
}

// ============================================================================
// State init (index 1 = "prev" for step 0); c-states now live in registers.
// ============================================================================
__global__ void init_state()
{
    int i = blockIdx.x * blockDim.x + threadIdx.x;
    if (i >= BB * HH) return;
    int b = i >> 9, h = i & 511;
    bsplit(g_hx[b * 1024 + h],       g_H0h[1][i], g_H0l[1][i]);
    bsplit(g_hx[b * 1024 + 512 + h], g_H1h[1][i], g_H1l[1][i]);
    if (h < 128) {
        g_DECh[1][b * 128 + h] = __float2bfloat16(0.f);
        g_DECl[1][b * 128 + h] = __float2bfloat16(0.f);
        g_used[b * 128 + h] = 0;
    }
}

// ============================================================================
// fp32 SGEMM for the one-time FNN init
// ============================================================================
#define TBM 64
#define TBN 64
#define TBK 16
__global__ __launch_bounds__(256) void sgemm_bias(
    const float* __restrict__ A, const float* __restrict__ Bm,
    const float* __restrict__ bias, float* __restrict__ C,
    int M, int N, int K, int lda, int relu)
{
    __shared__ __align__(16) float As[TBK][TBM + 4];
    __shared__ __align__(16) float Bs[TBK][TBN + 4];
    const int t = threadIdx.x;
    const int bM = blockIdx.y * TBM, bN = blockIdx.x * TBN;
    const int tx = t & 15, ty = t >> 4;
    const int arow = t >> 2, ak = (t & 3) * 4;
    const int bk = t >> 4, bn = (t & 15) * 4;
    float acc[4][4];
#pragma unroll
    for (int i = 0; i < 4; i++)
#pragma unroll
        for (int j = 0; j < 4; j++) acc[i][j] = 0.f;
    for (int k0 = 0; k0 < K; k0 += TBK) {
        float4 a4 = *reinterpret_cast<const float4*>(A + (long)(bM + arow) * lda + k0 + ak);
        As[ak + 0][arow] = a4.x; As[ak + 1][arow] = a4.y;
        As[ak + 2][arow] = a4.z; As[ak + 3][arow] = a4.w;
        *reinterpret_cast<float4*>(&Bs[bk][bn]) =
            *reinterpret_cast<const float4*>(Bm + (long)(k0 + bk) * N + bN + bn);
        __syncthreads();
#pragma unroll
        for (int kk = 0; kk < TBK; kk++) {
            float4 av = *reinterpret_cast<const float4*>(&As[kk][ty * 4]);
            float4 bv = *reinterpret_cast<const float4*>(&Bs[kk][tx * 4]);
            float a[4] = {av.x, av.y, av.z, av.w};
            float b[4] = {bv.x, bv.y, bv.z, bv.w};
#pragma unroll
            for (int i = 0; i < 4; i++)
#pragma unroll
                for (int j = 0; j < 4; j++) acc[i][j] = fmaf(a[i], b[j], acc[i][j]);
        }
        __syncthreads();
    }
    float4 bv = *reinterpret_cast<const float4*>(bias + bN + tx * 4);
    float bb[4] = {bv.x, bv.y, bv.z, bv.w};
#pragma unroll
    for (int i = 0; i < 4; i++) {
        float4 o;
        o.x = acc[i][0] + bb[0]; o.y = acc[i][1] + bb[1];
        o.z = acc[i][2] + bb[2]; o.w = acc[i][3] + bb[3];
        if (relu) { o.x = fmaxf(o.x, 0.f); o.y = fmaxf(o.y, 0.f);
                    o.z = fmaxf(o.z, 0.f); o.w = fmaxf(o.w, 0.f); }
        *reinterpret_cast<float4*>(C + (long)(bM + ty * 4 + i) * N + bN + tx * 4) = o;
    }
}

// ============================================================================
// Persistent decode loop: 128 CTAs x 512 threads (16 warps, warp grid 2x8,
// warp tile 16x16). CTA tile 32(M)x128(N). KC=64 double-buffered cp.async.
// 3-pass hi/lo bf16 HMMA, LSTM cell in epilogue, c-state in registers.
// stage = Ah 4K | Al 4K | Bh 16K | Bl 16K = 40K; x2 = 80K dynamic smem.
// ============================================================================
#define STAGE 40960
#define GEMM_SMEM (2 * STAGE + 1024)

__device__ __forceinline__ void load_stage(uint32_t sbase,
    const __nv_bfloat16* A1h, const __nv_bfloat16* A1l, int str1, int ksplit,
    const __nv_bfloat16* A2h, const __nv_bfloat16* A2l, int str2,
    const __nv_bfloat16* Wh,  const __nv_bfloat16* Wl,  int K,
    int k0, int mt, int nt, int t)
{
    // A tiles: 256 threads hi, 256 threads lo
    {
        int tt = t & 255;
        int r = tt >> 3, cb = (tt & 7) << 4;
        int row = mt * 32 + r;
        bool hi = t < 256;
        const __nv_bfloat16* s1 = hi ? A1h : A1l;
        const __nv_bfloat16* s2 = hi ? A2h : A2l;
        const char* src = (k0 < ksplit)
            ? (const char*)(s1 + (long)row * str1 + k0) + cb
            : (const char*)(s2 + (long)row * str2 + (k0 - ksplit)) + cb;
        cp16(sbase + (hi ? 0 : 4096) + r * 128 + (cb ^ ((r & 7) << 4)), src);
    }
    // B tiles: 4 x 16B per thread
#pragma unroll
    for (int i = 0; i < 4; i++) {
        int idx = i * 512 + t;
        bool hi = idx < 1024;
        int j = hi ? idx : idx - 1024;
        int r = j >> 3, cb = (j & 7) << 4;
        cp16(sbase + (hi ? 8192 : 24576) + r * 128 + (cb ^ ((r & 7) << 4)),
             (const char*)((hi ? Wh : Wl) + (long)(nt * 128 + r) * K + k0) + cb);
    }
}

__device__ __forceinline__ void gemm_cell(uint32_t base,
    const __nv_bfloat16* A1h, const __nv_bfloat16* A1l, int str1, int ksplit,
    const __nv_bfloat16* A2h, const __nv_bfloat16* A2l, int str2,
    const __nv_bfloat16* Wh,  const __nv_bfloat16* Wl,  int K,
    float bi, float bf_, float bgg, float bo_,
    float* creg,
    __nv_bfloat16* __restrict__ hh, __nv_bfloat16* __restrict__ hl,
    float* __restrict__ hf, int mt, int nt)
{
    const int t = threadIdx.x;
    const int lane = t & 31, wid = t >> 5;
    const int wm = wid >> 3, wn = wid & 7;
    const int nch = K >> 6;

    float acc[2][4];
#pragma unroll
    for (int nf = 0; nf < 2; nf++)
#pragma unroll
        for (int v = 0; v < 4; v++) acc[nf][v] = 0.f;

    const int rA = wm * 16 + ((lane >> 3) & 1) * 8 + (lane & 7);
    const int cA = (lane >> 4) * 16;
    const int gB = lane >> 3;
    const int rB = wn * 16 + (gB >> 1) * 8 + (lane & 7);
    const int cB = (gB & 1) * 16;

    load_stage(base, A1h, A1l, str1, ksplit, A2h, A2l, str2, Wh, Wl, K, 0, mt, nt, t);
    CP_COMMIT();

    for (int c = 0; c < nch; c++) {
        if (c + 1 < nch) {
            load_stage(base + ((c + 1) & 1) * STAGE, A1h, A1l, str1, ksplit,
                       A2h, A2l, str2, Wh, Wl, K, (c + 1) * 64, mt, nt, t);
            CP_COMMIT();
            asm volatile("cp.async.wait_group 1;" ::: "memory");
        } else {
            asm volatile("cp.async.wait_group 0;" ::: "memory");
        }
        __syncthreads();

        uint32_t bb = base + (c & 1) * STAGE;
#pragma unroll
        for (int kk = 0; kk < 4; kk++) {
            uint32_t ah[4], al[4], bh[4], bl[4];
            uint32_t offA = (uint32_t)(rA * 128 + ((kk * 32 + cA) ^ ((rA & 7) << 4)));
            LDSM4(ah, bb + offA);
            LDSM4(al, bb + 4096 + offA);
            uint32_t offB = (uint32_t)(rB * 128 + ((kk * 32 + cB) ^ ((rB & 7) << 4)));
            LDSM4(bh, bb + 8192 + offB);
            LDSM4(bl, bb + 24576 + offB);
#pragma unroll
            for (int nf = 0; nf < 2; nf++) {
                mma16816(acc[nf], ah, bh + nf * 2);
                mma16816(acc[nf], ah, bl + nf * 2);
                mma16816(acc[nf], al, bh + nf * 2);
            }
        }
        __syncthreads();
    }

    // Epilogue: fragments are (i,f,g,o) of unit h for rows r0 and r0+8
    const int r0 = mt * 32 + wm * 16 + (lane >> 2);
    const int h = (nt * 8 + wn) * 4 + (lane & 3);
#pragma unroll
    for (int half = 0; half < 2; half++) {
        int b = r0 + half * 8;
        float iv = acc[0][half * 2 + 0] + bi;
        float fv = acc[0][half * 2 + 1] + bf_;
        float gv = acc[1][half * 2 + 0] + bgg;
        float ov = acc[1][half * 2 + 1] + bo_;
        float cn = sigf(fv) * creg[half] + sigf(iv) * tanhf(gv);
        creg[half] = cn;
        float hn = sigf(ov) * tanhf(cn);
        __nv_bfloat16 xh, xl;
        bsplit(hn, xh, xl);
        hh[(long)b * 512 + h] = xh;
        hl[(long)b * 512 + h] = xl;
        if (hf) hf[(long)b * 512 + h] = hn;
    }
}

__global__ __launch_bounds__(512, 1) void decode_loop(
    const float* __restrict__ node, const float* __restrict__ Wo,
    const float* __restrict__ bo, float* __restrict__ out)
{
    extern __shared__ char dsm[];
    uint32_t base = (smem_u32(dsm) + 1023) & ~1023u;
    __shared__ float s_h1[2 * 512];
    __shared__ float s_x[256], s_d[256];
    __shared__ int   s_i[256];

    const int t = threadIdx.x;
    const int bid = blockIdx.x;
    const int mt = bid >> 4, nt = bid & 15;
    const int lane = t & 31, wid = t >> 5;
    const int wn = wid & 7;

    // preload biases for this thread's unit (invariant across steps)
    const int C0 = nt * 128 + wn * 16;
    const int cu = lane & 3;
    const float b0i = g_bg0[C0 + 2 * cu],     b0f = g_bg0[C0 + 2 * cu + 1];
    const float b0g = g_bg0[C0 + 8 + 2 * cu], b0o = g_bg0[C0 + 8 + 2 * cu + 1];
    const float b1i = g_bg1[C0 + 2 * cu],     b1f = g_bg1[C0 + 2 * cu + 1];
    const float b1g = g_bg1[C0 + 8 + 2 * cu], b1o = g_bg1[C0 + 8 + 2 * cu + 1];

    float c0reg[2] = {0.f, 0.f}, c1reg[2] = {0.f, 0.f};

    unsigned* gf = &g_flags[mt][0];
    unsigned bt;
    asm("ld.global.u32 %0, [%1];" : "=r"(bt) : "l"(gf + nt));

    for (int s = 0; s < NNODES; s++) {
        const int cur = s & 1, prev = cur ^ 1;

        // Phase A: gates0 = [dec|h0] @ W0p -> cell0 -> H0[cur]
        gemm_cell(base, g_DECh[prev], g_DECl[prev], 128, 128,
                  g_H0h[prev], g_H0l[prev], 512,
                  g_W0h, g_W0l, 640,
                  b0i, b0f, b0g, b0o, c0reg,
                  g_H0h[cur], g_H0l[cur], nullptr, mt, nt);
        group_sync(gf, nt, ++bt);

        // Phase B: gates1 = [h0_new|h1_prev] @ W1p -> cell1 -> H1[cur] + h1f
        gemm_cell(base, g_H0h[cur], g_H0l[cur], 512, 512,
                  g_H1h[prev], g_H1l[prev], 512,
                  g_W1h, g_W1l, 1024,
                  b1i, b1f, b1g, b1o, c1reg,
                  g_H1h[cur], g_H1l[cur], g_h1f, mt, nt);
        group_sync(gf, nt, ++bt);

        // Tail: projection + masked argmin + scatter + dec feedback (2 batches/CTA)
        {
            const int q = t >> 7, n = t & 127;
            const bool act = q < 2;
            const int b = bid * 2 + q;
            if (act) {
#pragma unroll
                for (int j = 0; j < 4; j++)
                    s_h1[q * 512 + n + j * 128] = g_h1f[(long)b * 512 + n + j * 128];
            }
            __syncthreads();
            if (act) {
                float accp = bo[n];
                const float4* wr = reinterpret_cast<const float4*>(Wo + (long)n * 512);
                const float4* hv = reinterpret_cast<const float4*>(s_h1 + q * 512);
#pragma unroll 4
                for (int kq = 0; kq < 128; kq++) {
                    float4 w = wr[kq], h4 = hv[kq];
                    accp = fmaf(w.x, h4.x, accp); accp = fmaf(w.y, h4.y, accp);
                    accp = fmaf(w.z, h4.z, accp); accp = fmaf(w.w, h4.w, accp);
                }
                s_x[q * 128 + n] = accp;
            }
            __syncthreads();
            if (act) {
                float dist = 3.4e38f;
                if (!g_used[b * 128 + n]) {
                    const float* nd = node + ((long)b * 128 + n) * 128;
                    const float* xsb = s_x + q * 128;
                    float sum = 0.f;
#pragma unroll 8
                    for (int d = 0; d < 128; d++) {
                        float df = xsb[d] - nd[d];
                        sum = fmaf(df, df, sum);
                    }
                    dist = sum;
                }
                s_d[q * 128 + n] = dist;
                s_i[q * 128 + n] = n;
            }
            __syncthreads();
#pragma unroll
            for (int st_ = 64; st_ > 0; st_ >>= 1) {
                if (act && n < st_) {
                    float ov = s_d[q * 128 + n + st_]; int oi = s_i[q * 128 + n + st_];
                    if (ov < s_d[q * 128 + n] ||
                        (ov == s_d[q * 128 + n] && oi < s_i[q * 128 + n])) {
                        s_d[q * 128 + n] = ov; s_i[q * 128 + n] = oi;
                    }
                }
                __syncthreads();
            }
            if (act) {
                int idx = s_i[q * 128];
                if (n == 0) g_used[b * 128 + idx] = 1;
                float xv = s_x[q * 128 + n];
                out[((long)b * 128 + idx) * 128 + n] = xv;
                __nv_bfloat16 xh, xl;
                bsplit(xv, xh, xl);
                g_DECh[cur][b * 128 + n] = xh;
                g_DECl[cur][b * 128 + n] = xl;
            }
        }
        group_sync(gf, nt, ++bt);
    }
}

// ============================================================================
// Launch
// ============================================================================
extern "C" void kernel_launch(void* const* d_in, const int* in_sizes, int n_in,
                              void* d_out, int out_size)
{
    const float* emb  = (const float*)d_in[0];
    const float* node = (const float*)d_in[1];
    const float* W1   = (const float*)d_in[2];
    const float* b1   = (const float*)d_in[3];
    const float* W2   = (const float*)d_in[4];
    const float* b2   = (const float*)d_in[5];
    const float* Wih0 = (const float*)d_in[6];
    const float* Whh0 = (const float*)d_in[7];
    const float* bih0 = (const float*)d_in[8];
    const float* bhh0 = (const float*)d_in[9];
    const float* Wih1 = (const float*)d_in[10];
    const float* Whh1 = (const float*)d_in[11];
    const float* bih1 = (const float*)d_in[12];
    const float* bhh1 = (const float*)d_in[13];
    const float* Wo   = (const float*)d_in[14];
    const float* bo   = (const float*)d_in[15];
    float* out = (float*)d_out;

    cudaFuncSetAttribute(decode_loop, cudaFuncAttributeMaxDynamicSharedMemorySize, GEMM_SMEM);

    float *pW1ft, *pW2ft, *pt, *phx;
    cudaGetSymbolAddress((void**)&pW1ft, g_W1ft);
    cudaGetSymbolAddress((void**)&pW2ft, g_W2ft);
    cudaGetSymbolAddress((void**)&pt,    g_t);
    cudaGetSymbolAddress((void**)&phx,   g_hx);

    prep_weights<<<2048, 256>>>(Wih0, Whh0, bih0, bhh0, Wih1, Whh1, bih1, bhh1, W1, W2);
    sgemm_bias<<<dim3(512 / TBN, BB / TBM), 256>>>(emb, pW1ft, b1, pt, BB, 512, 512, 512, 1);
    sgemm_bias<<<dim3(1024 / TBN, BB / TBM), 256>>>(pt, pW2ft, b2, phx, BB, 1024, 512, 512, 0);
    init_state<<<(BB * HH) / 256, 256>>>();

    decode_loop<<<NCTA, 512, GEMM_SMEM>>>(node, Wo, bo, out);
}

// round 7
// speedup vs baseline: 1.1054x; 1.1054x over previous
#include <cuda_runtime.h>
#include <cuda_bf16.h>
#include <math.h>
#include <stdint.h>

#define BB 256
#define HH 512
#define NNODES 128
#define NCTA 128

// ============================================================================
// PTX helpers (sm_80+ only — tcgen05 is sm_103a-gated, harness emits compute_103)
// ============================================================================
__device__ __forceinline__ uint32_t smem_u32(const void* p) {
    uint32_t a;
    asm("{ .reg .u64 t; cvta.to.shared.u64 t, %1; cvt.u32.u64 %0, t; }" : "=r"(a) : "l"(p));
    return a;
}
__device__ __forceinline__ void cp16(uint32_t saddr, const void* g) {
    asm volatile("cp.async.cg.shared.global [%0], [%1], 16;" :: "r"(saddr), "l"(g));
}
#define CP_COMMIT() asm volatile("cp.async.commit_group;" ::: "memory")
#define CP_WAIT0()  asm volatile("cp.async.wait_group 0;" ::: "memory")
#define LDSM4(r, a) asm volatile("ldmatrix.sync.aligned.m8n8.x4.shared.b16 {%0,%1,%2,%3}, [%4];" \
    : "=r"((r)[0]), "=r"((r)[1]), "=r"((r)[2]), "=r"((r)[3]) : "r"(a))

__device__ __forceinline__ void mma16816(float* c, const uint32_t* a, const uint32_t* b) {
    asm volatile("mma.sync.aligned.m16n8k16.row.col.f32.bf16.bf16.f32 "
                 "{%0,%1,%2,%3}, {%4,%5,%6,%7}, {%8,%9}, {%0,%1,%2,%3};"
                 : "+f"(c[0]), "+f"(c[1]), "+f"(c[2]), "+f"(c[3])
                 : "r"(a[0]), "r"(a[1]), "r"(a[2]), "r"(a[3]), "r"(b[0]), "r"(b[1]));
}

// ============================================================================
// Device globals
// ============================================================================
__device__ __align__(16) __nv_bfloat16 g_W0h[2048 * 640],  g_W0l[2048 * 640];
__device__ __align__(16) __nv_bfloat16 g_W1h[2048 * 1024], g_W1l[2048 * 1024];
__device__ __align__(16) float g_W1ft[512 * 512], g_W2ft[512 * 1024];
__device__ __align__(16) float g_bg0[2048], g_bg1[2048];
__device__ __align__(16) __nv_bfloat16 g_H0h[2][BB * HH], g_H0l[2][BB * HH];
__device__ __align__(16) __nv_bfloat16 g_H1h[2][BB * HH], g_H1l[2][BB * HH];
__device__ __align__(16) __nv_bfloat16 g_DECh[2][BB * 128], g_DECl[2][BB * 128];
__device__ __align__(16) float g_h1f[BB * HH];
__device__ __align__(16) float g_t[BB * 512], g_hx[BB * 1024];
__device__ unsigned char g_used[BB * NNODES];
// per-mt-group flag barriers (monotonic across graph replays)
__device__ __align__(64) unsigned g_flags[8][16];

__device__ __forceinline__ void bsplit(float x, __nv_bfloat16& h, __nv_bfloat16& l) {
    h = __float2bfloat16(x);
    l = __float2bfloat16(x - __bfloat162float(h));
}
__device__ __forceinline__ float sigf(float v) { return 1.f / (1.f + expf(-v)); }

// 16-CTA group barrier: write own flag (release), poll group's 16 flags (acquire)
__device__ __forceinline__ void group_sync(unsigned* gf, int nt, unsigned target) {
    __syncthreads();
    if (threadIdx.x == 0)
        asm volatile("st.release.gpu.global.u32 [%0], %1;" :: "l"(gf + nt), "r"(target) : "memory");
    if (threadIdx.x < 16) {
        unsigned v;
        do {
            asm volatile("ld.acquire.gpu.global.u32 %0, [%1];"
                         : "=r"(v) : "l"(gf + threadIdx.x) : "memory");
        } while (v < target);
    }
    __syncthreads();
}

// ============================================================================
// Weight prep. Packed column layout: pc = G*32 + gate*8 + u  (G=h/8, u=h%8),
// n_orig = gate*512 + G*8 + u. One warp's 32 cols = all 4 gates of 8 hidden.
// ============================================================================
__global__ void prep_weights(const float* __restrict__ Wih0, const float* __restrict__ Whh0,
                             const float* __restrict__ bih0, const float* __restrict__ bhh0,
                             const float* __restrict__ Wih1, const float* __restrict__ Whh1,
                             const float* __restrict__ bih1, const float* __restrict__ bhh1,
                             const float* __restrict__ W1,   const float* __restrict__ W2)
{
    const long S0 = 2048L * 640;
    const long S1 = S0 + 2048L * 1024;
    const long S2 = S1 + 512L * 512;
    const long S3 = S2 + 512L * 1024;
    const long S4 = S3 + 2048;
    const long S5 = S4 + 2048;
    long stride = (long)gridDim.x * blockDim.x;
    for (long i = (long)blockIdx.x * blockDim.x + threadIdx.x; i < S5; i += stride) {
        if (i < S0) {
            long r = i; int pc = (int)(r / 640), k = (int)(r % 640);
            int n = ((pc >> 3) & 3) * 512 + (pc >> 5) * 8 + (pc & 7);
            float w = (k < 128) ? Wih0[(long)n * 128 + k] : Whh0[(long)n * 512 + (k - 128)];
            bsplit(w, g_W0h[r], g_W0l[r]);
        } else if (i < S1) {
            long r = i - S0; int pc = (int)(r / 1024), k = (int)(r % 1024);
            int n = ((pc >> 3) & 3) * 512 + (pc >> 5) * 8 + (pc & 7);
            float w = (k < 512) ? Wih1[(long)n * 512 + k] : Whh1[(long)n * 512 + (k - 512)];
            bsplit(w, g_W1h[r], g_W1l[r]);
        } else if (i < S2) {
            long r = i - S1; int k = (int)(r / 512), j = (int)(r % 512);
            g_W1ft[r] = W1[(long)j * 512 + k];
        } else if (i < S3) {
            long r = i - S2; int k = (int)(r / 1024), j = (int)(r % 1024);
            g_W2ft[r] = W2[(long)j * 512 + k];
        } else if (i < S4) {
            int pc = (int)(i - S3);
            int n = ((pc >> 3) & 3) * 512 + (pc >> 5) * 8 + (pc & 7);
            g_bg0[pc] = bih0[n] + bhh0[n];
        } else {
            int pc = (int)(i - S4);
            int n = ((pc >> 3) & 3) * 512 + (pc >> 5) * 8 + (pc & 7);
            g_bg1[pc] = bih1[n] + bhh1[n];
        }
    }
}

// ============================================================================
// State init (index 1 = "prev" for step 0); c-states live in registers.
// ============================================================================
__global__ void init_state()
{
    int i = blockIdx.x * blockDim.x + threadIdx.x;
    if (i >= BB * HH) return;
    int b = i >> 9, h = i & 511;
    bsplit(g_hx[b * 1024 + h],       g_H0h[1][i], g_H0l[1][i]);
    bsplit(g_hx[b * 1024 + 512 + h], g_H1h[1][i], g_H1l[1][i]);
    if (h < 128) {
        g_DECh[1][b * 128 + h] = __float2bfloat16(0.f);
        g_DECl[1][b * 128 + h] = __float2bfloat16(0.f);
        g_used[b * 128 + h] = 0;
    }
}

// ============================================================================
// fp32 SGEMM for the one-time FNN init
// ============================================================================
#define TBM 64
#define TBN 64
#define TBK 16
__global__ __launch_bounds__(256) void sgemm_bias(
    const float* __restrict__ A, const float* __restrict__ Bm,
    const float* __restrict__ bias, float* __restrict__ C,
    int M, int N, int K, int lda, int relu)
{
    __shared__ __align__(16) float As[TBK][TBM + 4];
    __shared__ __align__(16) float Bs[TBK][TBN + 4];
    const int t = threadIdx.x;
    const int bM = blockIdx.y * TBM, bN = blockIdx.x * TBN;
    const int tx = t & 15, ty = t >> 4;
    const int arow = t >> 2, ak = (t & 3) * 4;
    const int bk = t >> 4, bn = (t & 15) * 4;
    float acc[4][4];
#pragma unroll
    for (int i = 0; i < 4; i++)
#pragma unroll
        for (int j = 0; j < 4; j++) acc[i][j] = 0.f;
    for (int k0 = 0; k0 < K; k0 += TBK) {
        float4 a4 = *reinterpret_cast<const float4*>(A + (long)(bM + arow) * lda + k0 + ak);
        As[ak + 0][arow] = a4.x; As[ak + 1][arow] = a4.y;
        As[ak + 2][arow] = a4.z; As[ak + 3][arow] = a4.w;
        *reinterpret_cast<float4*>(&Bs[bk][bn]) =
            *reinterpret_cast<const float4*>(Bm + (long)(k0 + bk) * N + bN + bn);
        __syncthreads();
#pragma unroll
        for (int kk = 0; kk < TBK; kk++) {
            float4 av = *reinterpret_cast<const float4*>(&As[kk][ty * 4]);
            float4 bv = *reinterpret_cast<const float4*>(&Bs[kk][tx * 4]);
            float a[4] = {av.x, av.y, av.z, av.w};
            float b[4] = {bv.x, bv.y, bv.z, bv.w};
#pragma unroll
            for (int i = 0; i < 4; i++)
#pragma unroll
                for (int j = 0; j < 4; j++) acc[i][j] = fmaf(a[i], b[j], acc[i][j]);
        }
        __syncthreads();
    }
    float4 bv = *reinterpret_cast<const float4*>(bias + bN + tx * 4);
    float bb[4] = {bv.x, bv.y, bv.z, bv.w};
#pragma unroll
    for (int i = 0; i < 4; i++) {
        float4 o;
        o.x = acc[i][0] + bb[0]; o.y = acc[i][1] + bb[1];
        o.z = acc[i][2] + bb[2]; o.w = acc[i][3] + bb[3];
        if (relu) { o.x = fmaxf(o.x, 0.f); o.y = fmaxf(o.y, 0.f);
                    o.z = fmaxf(o.z, 0.f); o.w = fmaxf(o.w, 0.f); }
        *reinterpret_cast<float4*>(C + (long)(bM + ty * 4 + i) * N + bN + tx * 4) = o;
    }
}

// ============================================================================
// Persistent decode loop: 128 CTAs x 256 threads (8 warps, warp grid 2x4,
// warp tile 16x32). CTA tile 32(M)x128(N). KC=128 (two 64-wide panels per
// stage), double-buffered cp.async, ONE __syncthreads per chunk, register
// double-buffered fragments, pass-major HMMA interleave, c-state in regs.
// stage = Ah 8K | Al 8K | Bh 32K | Bl 32K = 80K; x2 = 160K dynamic smem.
// ============================================================================
#define KC 128
#define STAGE 81920
#define GEMM_SMEM (2 * STAGE + 1024)

__device__ __forceinline__ void load_A(uint32_t dst,
    const __nv_bfloat16* __restrict__ s1, int str1, int ksplit,
    const __nv_bfloat16* __restrict__ s2, int str2, int k0, int mt, int t)
{
#pragma unroll
    for (int i = 0; i < 2; i++) {
        int idx = i * 256 + t;
        int r = idx >> 4;              // 0..31
        int v = idx & 15;              // vec16 within 128-elem row
        int panel = v >> 3, c = (v & 7) << 4;
        int k = k0 + v * 8;
        int row = mt * 32 + r;
        const char* src = (k < ksplit)
            ? (const char*)(s1 + (long)row * str1 + k)
            : (const char*)(s2 + (long)row * str2 + (k - ksplit));
        cp16(dst + panel * 4096 + r * 128 + (c ^ ((r & 7) << 4)), src);
    }
}
__device__ __forceinline__ void load_B(uint32_t dst, const __nv_bfloat16* __restrict__ w,
                                       int K, int k0, int nt, int t)
{
#pragma unroll
    for (int i = 0; i < 8; i++) {
        int idx = i * 256 + t;
        int r = idx >> 4;              // 0..127
        int v = idx & 15;
        int panel = v >> 3, c = (v & 7) << 4;
        cp16(dst + panel * 16384 + r * 128 + (c ^ ((r & 7) << 4)),
             (const char*)(w + (long)(nt * 128 + r) * K + k0 + v * 8));
    }
}

__device__ __forceinline__ void gemm_cell(uint32_t base,
    const __nv_bfloat16* A1h, const __nv_bfloat16* A1l, int str1, int ksplit,
    const __nv_bfloat16* A2h, const __nv_bfloat16* A2l, int str2,
    const __nv_bfloat16* Wh,  const __nv_bfloat16* Wl,  int K,
    const float2* bi,           // bi[4]: per-gate (u0,u1) biases
    float* creg,                // creg[4]: [half*2+u]
    __nv_bfloat16* __restrict__ hh, __nv_bfloat16* __restrict__ hl,
    float* __restrict__ hf, int mt, int nt)
{
    const int t = threadIdx.x;
    const int lane = t & 31, wid = t >> 5;
    const int wm = wid >> 2, wn = wid & 3;
    const int nch = K >> 7;

    float acc[4][4];
#pragma unroll
    for (int j = 0; j < 4; j++)
#pragma unroll
        for (int v = 0; v < 4; v++) acc[j][v] = 0.f;

    const int rA = wm * 16 + ((lane >> 3) & 1) * 8 + (lane & 7);
    const int cA = (lane >> 4) * 16;
    const int gB = lane >> 3;
    const int rBb = (gB >> 1) * 8 + (lane & 7);
    const int cB = (gB & 1) * 16;

    // prologue: chunk 0
    load_A(base,        A1h, str1, ksplit, A2h, str2, 0, mt, t);
    load_A(base + 8192, A1l, str1, ksplit, A2l, str2, 0, mt, t);
    load_B(base + 16384, Wh, K, 0, nt, t);
    load_B(base + 49152, Wl, K, 0, nt, t);
    CP_COMMIT();

    uint32_t frag[2][24];   // [buf][ ah:0-3 | al:4-7 | bh:8-15 | bl:16-23 ]

    for (int c = 0; c < nch; c++) {
        CP_WAIT0();
        __syncthreads();
        if (c + 1 < nch) {
            uint32_t nb = base + ((c + 1) & 1) * STAGE;
            int k0 = (c + 1) * KC;
            load_A(nb,        A1h, str1, ksplit, A2h, str2, k0, mt, t);
            load_A(nb + 8192, A1l, str1, ksplit, A2l, str2, k0, mt, t);
            load_B(nb + 16384, Wh, K, k0, nt, t);
            load_B(nb + 49152, Wl, K, k0, nt, t);
            CP_COMMIT();
        }
        const uint32_t bb = base + (c & 1) * STAGE;

        // fragment loader for sub-step kk (0..7)
#define LDFRAG(F, KK) do {                                                        \
            int _panel = (KK) >> 2, _k2 = (KK) & 3;                               \
            uint32_t _offA = (uint32_t)(_panel * 4096 + rA * 128 +                \
                             ((_k2 * 32 + cA) ^ ((rA & 7) << 4)));                \
            LDSM4((F) + 0, bb + _offA);                                           \
            LDSM4((F) + 4, bb + 8192 + _offA);                                    \
            _Pragma("unroll")                                                     \
            for (int _jj = 0; _jj < 2; _jj++) {                                   \
                int _r = wn * 32 + _jj * 16 + rBb;                                \
                uint32_t _offB = (uint32_t)(_panel * 16384 + _r * 128 +           \
                                 ((_k2 * 32 + cB) ^ ((_r & 7) << 4)));            \
                LDSM4((F) + 8 + _jj * 4,  bb + 16384 + _offB);                    \
                LDSM4((F) + 16 + _jj * 4, bb + 49152 + _offB);                    \
            }                                                                     \
        } while (0)

        LDFRAG(frag[0], 0);
#pragma unroll
        for (int kk = 0; kk < 8; kk++) {
            if (kk < 7) LDFRAG(frag[(kk + 1) & 1], kk + 1);
            uint32_t* f = frag[kk & 1];
            // pass-major interleave: per-acc order stays hh, hl, lh
#pragma unroll
            for (int j = 0; j < 4; j++)
                mma16816(acc[j], f,     f + 8  + (j >> 1) * 4 + (j & 1) * 2);
#pragma unroll
            for (int j = 0; j < 4; j++)
                mma16816(acc[j], f,     f + 16 + (j >> 1) * 4 + (j & 1) * 2);
#pragma unroll
            for (int j = 0; j < 4; j++)
                mma16816(acc[j], f + 4, f + 8  + (j >> 1) * 4 + (j & 1) * 2);
        }
#undef LDFRAG
    }
    __syncthreads();

    // Epilogue: LSTM cell from fragments. thread owns rows (b0, b0+8),
    // units (h0i, h0i+1); gates j=0..3 in acc[j].
    const int b0 = mt * 32 + wm * 16 + (lane >> 2);
    const int h0i = (nt * 4 + wn) * 8 + 2 * (lane & 3);
#pragma unroll
    for (int half = 0; half < 2; half++) {
        int b = b0 + half * 8;
        float hn[2];
#pragma unroll
        for (int u = 0; u < 2; u++) {
            int v = half * 2 + u;
            float iv = acc[0][v] + (u ? bi[0].y : bi[0].x);
            float fv = acc[1][v] + (u ? bi[1].y : bi[1].x);
            float gv = acc[2][v] + (u ? bi[2].y : bi[2].x);
            float ov = acc[3][v] + (u ? bi[3].y : bi[3].x);
            float cn = sigf(fv) * creg[v] + sigf(iv) * tanhf(gv);
            creg[v] = cn;
            hn[u] = sigf(ov) * tanhf(cn);
        }
        __nv_bfloat16 h0h, h0l, h1h2, h1l2;
        bsplit(hn[0], h0h, h0l);
        bsplit(hn[1], h1h2, h1l2);
        long hi = (long)b * 512 + h0i;
        *reinterpret_cast<__nv_bfloat162*>(hh + hi) = __nv_bfloat162(h0h, h1h2);
        *reinterpret_cast<__nv_bfloat162*>(hl + hi) = __nv_bfloat162(h0l, h1l2);
        if (hf) *reinterpret_cast<float2*>(hf + hi) = make_float2(hn[0], hn[1]);
    }
}

__global__ __launch_bounds__(256, 1) void decode_loop(
    const float* __restrict__ node, const float* __restrict__ Wo,
    const float* __restrict__ bo, float* __restrict__ out)
{
    extern __shared__ char dsm[];
    uint32_t base = (smem_u32(dsm) + 1023) & ~1023u;
    __shared__ float s_h1[1024];
    __shared__ float s_x[256], s_d[256];
    __shared__ int   s_i[256];

    const int t = threadIdx.x;
    const int bid = blockIdx.x;
    const int mt = bid >> 4, nt = bid & 15;
    const int lane = t & 31, wid = t >> 5;
    const int wm = wid >> 2, wn = wid & 3;
    const int q = t >> 7, n = t & 127;

    // preload biases for this thread's packed columns (static across steps)
    const int pcb = nt * 128 + wn * 32 + 2 * (lane & 3);
    float2 bi0[4], bi1[4];
#pragma unroll
    for (int j = 0; j < 4; j++) {
        bi0[j] = make_float2(g_bg0[pcb + j * 8], g_bg0[pcb + j * 8 + 1]);
        bi1[j] = make_float2(g_bg1[pcb + j * 8], g_bg1[pcb + j * 8 + 1]);
    }
    float c0reg[4] = {0.f, 0.f, 0.f, 0.f};
    float c1reg[4] = {0.f, 0.f, 0.f, 0.f};
    (void)wm;

    unsigned* gf = &g_flags[mt][0];
    unsigned bt;
    asm("ld.global.u32 %0, [%1];" : "=r"(bt) : "l"(gf + nt));

    for (int s = 0; s < NNODES; s++) {
        const int cur = s & 1, prev = cur ^ 1;

        // Phase A: gates0 = [dec|h0] @ W0p -> cell0 -> H0[cur]
        gemm_cell(base, g_DECh[prev], g_DECl[prev], 128, 128,
                  g_H0h[prev], g_H0l[prev], 512,
                  g_W0h, g_W0l, 640, bi0, c0reg,
                  g_H0h[cur], g_H0l[cur], nullptr, mt, nt);
        group_sync(gf, nt, ++bt);

        // Phase B: gates1 = [h0_new|h1_prev] @ W1p -> cell1 -> H1[cur] + h1f
        gemm_cell(base, g_H0h[cur], g_H0l[cur], 512, 512,
                  g_H1h[prev], g_H1l[prev], 512,
                  g_W1h, g_W1l, 1024, bi1, c1reg,
                  g_H1h[cur], g_H1l[cur], g_h1f, mt, nt);
        group_sync(gf, nt, ++bt);

        // Tail: projection + masked argmin + scatter + dec feedback (2 batches/CTA)
        {
            const int b = bid * 2 + q;
#pragma unroll
            for (int j = 0; j < 4; j++)
                s_h1[q * 512 + n + j * 128] = g_h1f[(long)b * 512 + n + j * 128];
            __syncthreads();
            float accp = bo[n];
            const float4* wr = reinterpret_cast<const float4*>(Wo + (long)n * 512);
            const float4* hv = reinterpret_cast<const float4*>(s_h1 + q * 512);
#pragma unroll 4
            for (int kq = 0; kq < 128; kq++) {
                float4 w = wr[kq], h4 = hv[kq];
                accp = fmaf(w.x, h4.x, accp); accp = fmaf(w.y, h4.y, accp);
                accp = fmaf(w.z, h4.z, accp); accp = fmaf(w.w, h4.w, accp);
            }
            s_x[q * 128 + n] = accp;
            __syncthreads();
            float dist = 3.4e38f;
            if (!g_used[b * 128 + n]) {
                const float* nd = node + ((long)b * 128 + n) * 128;
                const float* xsb = s_x + q * 128;
                float sum = 0.f;
#pragma unroll 8
                for (int d = 0; d < 128; d++) {
                    float df = xsb[d] - nd[d];
                    sum = fmaf(df, df, sum);
                }
                dist = sum;
            }
            s_d[q * 128 + n] = dist;
            s_i[q * 128 + n] = n;
            __syncthreads();
#pragma unroll
            for (int st_ = 64; st_ > 0; st_ >>= 1) {
                if (n < st_) {
                    float ov = s_d[q * 128 + n + st_]; int oi = s_i[q * 128 + n + st_];
                    if (ov < s_d[q * 128 + n] ||
                        (ov == s_d[q * 128 + n] && oi < s_i[q * 128 + n])) {
                        s_d[q * 128 + n] = ov; s_i[q * 128 + n] = oi;
                    }
                }
                __syncthreads();
            }
            int idx = s_i[q * 128];
            if (n == 0) g_used[b * 128 + idx] = 1;
            float xv = s_x[q * 128 + n];
            out[((long)b * 128 + idx) * 128 + n] = xv;
            __nv_bfloat16 xh, xl;
            bsplit(xv, xh, xl);
            g_DECh[cur][b * 128 + n] = xh;
            g_DECl[cur][b * 128 + n] = xl;
        }
        group_sync(gf, nt, ++bt);
    }
}

// ============================================================================
// Launch
// ============================================================================
extern "C" void kernel_launch(void* const* d_in, const int* in_sizes, int n_in,
                              void* d_out, int out_size)
{
    const float* emb  = (const float*)d_in[0];
    const float* node = (const float*)d_in[1];
    const float* W1   = (const float*)d_in[2];
    const float* b1   = (const float*)d_in[3];
    const float* W2   = (const float*)d_in[4];
    const float* b2   = (const float*)d_in[5];
    const float* Wih0 = (const float*)d_in[6];
    const float* Whh0 = (const float*)d_in[7];
    const float* bih0 = (const float*)d_in[8];
    const float* bhh0 = (const float*)d_in[9];
    const float* Wih1 = (const float*)d_in[10];
    const float* Whh1 = (const float*)d_in[11];
    const float* bih1 = (const float*)d_in[12];
    const float* bhh1 = (const float*)d_in[13];
    const float* Wo   = (const float*)d_in[14];
    const float* bo   = (const float*)d_in[15];
    float* out = (float*)d_out;

    cudaFuncSetAttribute(decode_loop, cudaFuncAttributeMaxDynamicSharedMemorySize, GEMM_SMEM);

    float *pW1ft, *pW2ft, *pt, *phx;
    cudaGetSymbolAddress((void**)&pW1ft, g_W1ft);
    cudaGetSymbolAddress((void**)&pW2ft, g_W2ft);
    cudaGetSymbolAddress((void**)&pt,    g_t);
    cudaGetSymbolAddress((void**)&phx,   g_hx);

    prep_weights<<<2048, 256>>>(Wih0, Whh0, bih0, bhh0, Wih1, Whh1, bih1, bhh1, W1, W2);
    sgemm_bias<<<dim3(512 / TBN, BB / TBM), 256>>>(emb, pW1ft, b1, pt, BB, 512, 512, 512, 1);
    sgemm_bias<<<dim3(1024 / TBN, BB / TBM), 256>>>(pt, pW2ft, b2, phx, BB, 1024, 512, 512, 0);
    init_state<<<(BB * HH) / 256, 256>>>();

    decode_loop<<<NCTA, 256, GEMM_SMEM>>>(node, Wo, bo, out);
}

// round 8
// speedup vs baseline: 1.1258x; 1.0185x over previous
#include <cuda_runtime.h>
#include <cuda_bf16.h>
#include <math.h>
#include <stdint.h>

#define BB 256
#define HH 512
#define NNODES 128
#define NCTA 128

// ============================================================================
// PTX helpers (sm_80+ only — tcgen05 is sm_103a-gated, harness emits compute_103)
// ============================================================================
__device__ __forceinline__ uint32_t smem_u32(const void* p) {
    uint32_t a;
    asm("{ .reg .u64 t; cvta.to.shared.u64 t, %1; cvt.u32.u64 %0, t; }" : "=r"(a) : "l"(p));
    return a;
}
__device__ __forceinline__ void cp16(uint32_t saddr, const void* g) {
    asm volatile("cp.async.cg.shared.global [%0], [%1], 16;" :: "r"(saddr), "l"(g));
}
#define CP_COMMIT() asm volatile("cp.async.commit_group;" ::: "memory")
#define LDSM4(r, a) asm volatile("ldmatrix.sync.aligned.m8n8.x4.shared.b16 {%0,%1,%2,%3}, [%4];" \
    : "=r"((r)[0]), "=r"((r)[1]), "=r"((r)[2]), "=r"((r)[3]) : "r"(a))

__device__ __forceinline__ void mma16816(float* c, const uint32_t* a, const uint32_t* b) {
    asm volatile("mma.sync.aligned.m16n8k16.row.col.f32.bf16.bf16.f32 "
                 "{%0,%1,%2,%3}, {%4,%5,%6,%7}, {%8,%9}, {%0,%1,%2,%3};"
                 : "+f"(c[0]), "+f"(c[1]), "+f"(c[2]), "+f"(c[3])
                 : "r"(a[0]), "r"(a[1]), "r"(a[2]), "r"(a[3]), "r"(b[0]), "r"(b[1]));
}

// ============================================================================
// Device globals
// ============================================================================
__device__ __align__(16) __nv_bfloat16 g_W0h[2048 * 640],  g_W0l[2048 * 640];
__device__ __align__(16) __nv_bfloat16 g_W1h[2048 * 1024], g_W1l[2048 * 1024];
__device__ __align__(16) float g_W1ft[512 * 512], g_W2ft[512 * 1024];
__device__ __align__(16) float g_bg0[2048], g_bg1[2048];
__device__ __align__(16) __nv_bfloat16 g_H0h[2][BB * HH], g_H0l[2][BB * HH];
__device__ __align__(16) __nv_bfloat16 g_H1h[2][BB * HH], g_H1l[2][BB * HH];
__device__ __align__(16) __nv_bfloat16 g_DECh[2][BB * 128], g_DECl[2][BB * 128];
__device__ __align__(16) float g_h1f[BB * HH];
__device__ __align__(16) float g_t[BB * 512], g_hx[BB * 1024];
__device__ unsigned char g_used[BB * NNODES];
// per-mt-group flag barriers (monotonic across graph replays)
__device__ __align__(64) unsigned g_flags[8][16];

__device__ __forceinline__ void bsplit(float x, __nv_bfloat16& h, __nv_bfloat16& l) {
    h = __float2bfloat16(x);
    l = __float2bfloat16(x - __bfloat162float(h));
}
__device__ __forceinline__ float sigf(float v) { return 1.f / (1.f + expf(-v)); }

// 16-CTA group barrier: write own flag (release), poll group's 16 flags (acquire)
__device__ __forceinline__ void group_sync(unsigned* gf, int nt, unsigned target) {
    __syncthreads();
    if (threadIdx.x == 0)
        asm volatile("st.release.gpu.global.u32 [%0], %1;" :: "l"(gf + nt), "r"(target) : "memory");
    if (threadIdx.x < 16) {
        unsigned v;
        do {
            asm volatile("ld.acquire.gpu.global.u32 %0, [%1];"
                         : "=r"(v) : "l"(gf + threadIdx.x) : "memory");
        } while (v < target);
    }
    __syncthreads();
}

// ============================================================================
// Weight prep. Packed column layout: pc = G*32 + gate*8 + u  (G=h/8, u=h%8),
// n_orig = gate*512 + G*8 + u. One warp's 32 cols = all 4 gates of 8 hidden.
// ============================================================================
__global__ void prep_weights(const float* __restrict__ Wih0, const float* __restrict__ Whh0,
                             const float* __restrict__ bih0, const float* __restrict__ bhh0,
                             const float* __restrict__ Wih1, const float* __restrict__ Whh1,
                             const float* __restrict__ bih1, const float* __restrict__ bhh1,
                             const float* __restrict__ W1,   const float* __restrict__ W2)
{
    const long S0 = 2048L * 640;
    const long S1 = S0 + 2048L * 1024;
    const long S2 = S1 + 512L * 512;
    const long S3 = S2 + 512L * 1024;
    const long S4 = S3 + 2048;
    const long S5 = S4 + 2048;
    long stride = (long)gridDim.x * blockDim.x;
    for (long i = (long)blockIdx.x * blockDim.x + threadIdx.x; i < S5; i += stride) {
        if (i < S0) {
            long r = i; int pc = (int)(r / 640), k = (int)(r % 640);
            int n = ((pc >> 3) & 3) * 512 + (pc >> 5) * 8 + (pc & 7);
            float w = (k < 128) ? Wih0[(long)n * 128 + k] : Whh0[(long)n * 512 + (k - 128)];
            bsplit(w, g_W0h[r], g_W0l[r]);
        } else if (i < S1) {
            long r = i - S0; int pc = (int)(r / 1024), k = (int)(r % 1024);
            int n = ((pc >> 3) & 3) * 512 + (pc >> 5) * 8 + (pc & 7);
            float w = (k < 512) ? Wih1[(long)n * 512 + k] : Whh1[(long)n * 512 + (k - 512)];
            bsplit(w, g_W1h[r], g_W1l[r]);
        } else if (i < S2) {
            long r = i - S1; int k = (int)(r / 512), j = (int)(r % 512);
            g_W1ft[r] = W1[(long)j * 512 + k];
        } else if (i < S3) {
            long r = i - S2; int k = (int)(r / 1024), j = (int)(r % 1024);
            g_W2ft[r] = W2[(long)j * 512 + k];
        } else if (i < S4) {
            int pc = (int)(i - S3);
            int n = ((pc >> 3) & 3) * 512 + (pc >> 5) * 8 + (pc & 7);
            g_bg0[pc] = bih0[n] + bhh0[n];
        } else {
            int pc = (int)(i - S4);
            int n = ((pc >> 3) & 3) * 512 + (pc >> 5) * 8 + (pc & 7);
            g_bg1[pc] = bih1[n] + bhh1[n];
        }
    }
}

// ============================================================================
// State init (index 1 = "prev" for step 0); c-states live in registers.
// ============================================================================
__global__ void init_state()
{
    int i = blockIdx.x * blockDim.x + threadIdx.x;
    if (i >= BB * HH) return;
    int b = i >> 9, h = i & 511;
    bsplit(g_hx[b * 1024 + h],       g_H0h[1][i], g_H0l[1][i]);
    bsplit(g_hx[b * 1024 + 512 + h], g_H1h[1][i], g_H1l[1][i]);
    if (h < 128) {
        g_DECh[1][b * 128 + h] = __float2bfloat16(0.f);
        g_DECl[1][b * 128 + h] = __float2bfloat16(0.f);
        g_used[b * 128 + h] = 0;
    }
}

// ============================================================================
// fp32 SGEMM for the one-time FNN init
// ============================================================================
#define TBM 64
#define TBN 64
#define TBK 16
__global__ __launch_bounds__(256) void sgemm_bias(
    const float* __restrict__ A, const float* __restrict__ Bm,
    const float* __restrict__ bias, float* __restrict__ C,
    int M, int N, int K, int lda, int relu)
{
    __shared__ __align__(16) float As[TBK][TBM + 4];
    __shared__ __align__(16) float Bs[TBK][TBN + 4];
    const int t = threadIdx.x;
    const int bM = blockIdx.y * TBM, bN = blockIdx.x * TBN;
    const int tx = t & 15, ty = t >> 4;
    const int arow = t >> 2, ak = (t & 3) * 4;
    const int bk = t >> 4, bn = (t & 15) * 4;
    float acc[4][4];
#pragma unroll
    for (int i = 0; i < 4; i++)
#pragma unroll
        for (int j = 0; j < 4; j++) acc[i][j] = 0.f;
    for (int k0 = 0; k0 < K; k0 += TBK) {
        float4 a4 = *reinterpret_cast<const float4*>(A + (long)(bM + arow) * lda + k0 + ak);
        As[ak + 0][arow] = a4.x; As[ak + 1][arow] = a4.y;
        As[ak + 2][arow] = a4.z; As[ak + 3][arow] = a4.w;
        *reinterpret_cast<float4*>(&Bs[bk][bn]) =
            *reinterpret_cast<const float4*>(Bm + (long)(k0 + bk) * N + bN + bn);
        __syncthreads();
#pragma unroll
        for (int kk = 0; kk < TBK; kk++) {
            float4 av = *reinterpret_cast<const float4*>(&As[kk][ty * 4]);
            float4 bv = *reinterpret_cast<const float4*>(&Bs[kk][tx * 4]);
            float a[4] = {av.x, av.y, av.z, av.w};
            float b[4] = {bv.x, bv.y, bv.z, bv.w};
#pragma unroll
            for (int i = 0; i < 4; i++)
#pragma unroll
                for (int j = 0; j < 4; j++) acc[i][j] = fmaf(a[i], b[j], acc[i][j]);
        }
        __syncthreads();
    }
    float4 bv = *reinterpret_cast<const float4*>(bias + bN + tx * 4);
    float bb[4] = {bv.x, bv.y, bv.z, bv.w};
#pragma unroll
    for (int i = 0; i < 4; i++) {
        float4 o;
        o.x = acc[i][0] + bb[0]; o.y = acc[i][1] + bb[1];
        o.z = acc[i][2] + bb[2]; o.w = acc[i][3] + bb[3];
        if (relu) { o.x = fmaxf(o.x, 0.f); o.y = fmaxf(o.y, 0.f);
                    o.z = fmaxf(o.z, 0.f); o.w = fmaxf(o.w, 0.f); }
        *reinterpret_cast<float4*>(C + (long)(bM + ty * 4 + i) * N + bN + tx * 4) = o;
    }
}

// ============================================================================
// Persistent decode loop: 128 CTAs x 256 threads (8 warps, warp grid 2x4,
// warp tile 16x32). CTA tile 32(M)x128(N). KC=64 double-buffered cp.async
// (EXACT 7431-baseline chunk/sync structure). New vs baseline: pass-major
// HMMA order, fragment double-buffer across kk, c-state in registers,
// preloaded biases, 16-flag group barrier.
// stage = Ah 4K | Al 4K | Bh 16K | Bl 16K = 40K; x2 = 80K dynamic smem.
// ============================================================================
#define STAGE 40960
#define GEMM_SMEM (2 * STAGE + 1024)

__device__ __forceinline__ void load_a_tile(uint32_t sdst,
    const __nv_bfloat16* s1, int str1, int ksplit,
    const __nv_bfloat16* s2, int str2, int k0, int mt, int t)
{
    int r = t >> 3;
    int cb = (t & 7) << 4;
    int row = mt * 32 + r;
    const char* src = (k0 < ksplit)
        ? (const char*)(s1 + (long)row * str1 + k0) + cb
        : (const char*)(s2 + (long)row * str2 + (k0 - ksplit)) + cb;
    cp16(sdst + r * 128 + (cb ^ ((r & 7) << 4)), src);
}

__device__ __forceinline__ void load_b_tile(uint32_t sdst, const __nv_bfloat16* w,
                                            int K, int k0, int nt, int t)
{
#pragma unroll
    for (int i = 0; i < 4; i++) {
        int idx = i * 256 + t;
        int r = idx >> 3;
        int cb = (idx & 7) << 4;
        cp16(sdst + r * 128 + (cb ^ ((r & 7) << 4)),
             (const char*)(w + (long)(nt * 128 + r) * K + k0) + cb);
    }
}

__device__ __forceinline__ void gemm_cell_phase(uint32_t base,
    const __nv_bfloat16* A1h, const __nv_bfloat16* A1l, int str1, int ksplit,
    const __nv_bfloat16* A2h, const __nv_bfloat16* A2l, int str2,
    const __nv_bfloat16* Wh,  const __nv_bfloat16* Wl,  int K,
    const float2* bi,          // bi[4] per-gate (u0,u1) biases
    float* creg,               // creg[4] = c[half*2+u], register-resident
    __nv_bfloat16* __restrict__ hh, __nv_bfloat16* __restrict__ hl,
    float* __restrict__ hf, int mt, int nt)
{
    const int t = threadIdx.x;
    const int lane = t & 31, wid = t >> 5;
    const int wm = wid >> 2, wn = wid & 3;
    const int nch = K >> 6;

    float acc[4][4];
#pragma unroll
    for (int j = 0; j < 4; j++)
#pragma unroll
        for (int v = 0; v < 4; v++) acc[j][v] = 0.f;

    const int rA = wm * 16 + ((lane >> 3) & 1) * 8 + (lane & 7);
    const int cA = (lane >> 4) * 16;
    const int gB = lane >> 3;
    const int rBb = (gB >> 1) * 8 + (lane & 7);
    const int cB = (gB & 1) * 16;

    // prologue (identical to 7431 baseline)
    {
        load_a_tile(base,        A1h, str1, ksplit, A2h, str2, 0, mt, t);
        load_a_tile(base + 4096, A1l, str1, ksplit, A2l, str2, 0, mt, t);
        load_b_tile(base + 8192,  Wh, K, 0, nt, t);
        load_b_tile(base + 24576, Wl, K, 0, nt, t);
        CP_COMMIT();
    }

    uint32_t frag[2][24];   // [buf][ ah:0-3 | al:4-7 | bh:8-15 | bl:16-23 ]

    for (int c = 0; c < nch; c++) {
        if (c + 1 < nch) {
            uint32_t nb = base + ((c + 1) & 1) * STAGE;
            int k0 = (c + 1) * 64;
            load_a_tile(nb,        A1h, str1, ksplit, A2h, str2, k0, mt, t);
            load_a_tile(nb + 4096, A1l, str1, ksplit, A2l, str2, k0, mt, t);
            load_b_tile(nb + 8192,  Wh, K, k0, nt, t);
            load_b_tile(nb + 24576, Wl, K, k0, nt, t);
            CP_COMMIT();
            asm volatile("cp.async.wait_group 1;" ::: "memory");
        } else {
            asm volatile("cp.async.wait_group 0;" ::: "memory");
        }
        __syncthreads();

        const uint32_t bb = base + (c & 1) * STAGE;

#define LDFRAG(F, KK) do {                                                      \
            uint32_t _offA = (uint32_t)(rA * 128 +                              \
                             (((KK) * 32 + cA) ^ ((rA & 7) << 4)));             \
            LDSM4((F) + 0, bb + _offA);                                         \
            LDSM4((F) + 4, bb + 4096 + _offA);                                  \
            _Pragma("unroll")                                                   \
            for (int _jj = 0; _jj < 2; _jj++) {                                 \
                int _r = wn * 32 + _jj * 16 + rBb;                              \
                uint32_t _offB = (uint32_t)(_r * 128 +                          \
                                 (((KK) * 32 + cB) ^ ((_r & 7) << 4)));         \
                LDSM4((F) + 8 + _jj * 4,  bb + 8192 + _offB);                   \
                LDSM4((F) + 16 + _jj * 4, bb + 24576 + _offB);                  \
            }                                                                   \
        } while (0)

        LDFRAG(frag[0], 0);
#pragma unroll
        for (int kk = 0; kk < 4; kk++) {
            if (kk < 3) LDFRAG(frag[(kk + 1) & 1], kk + 1);
            uint32_t* f = frag[kk & 1];
            // pass-major interleave; per-acc order remains hh, hl, lh
#pragma unroll
            for (int j = 0; j < 4; j++)
                mma16816(acc[j], f,     f + 8  + (j >> 1) * 4 + (j & 1) * 2);
#pragma unroll
            for (int j = 0; j < 4; j++)
                mma16816(acc[j], f,     f + 16 + (j >> 1) * 4 + (j & 1) * 2);
#pragma unroll
            for (int j = 0; j < 4; j++)
                mma16816(acc[j], f + 4, f + 8  + (j >> 1) * 4 + (j & 1) * 2);
        }
#undef LDFRAG
        __syncthreads();
    }

    // Epilogue: LSTM cell from fragments; thread owns rows (b0, b0+8),
    // units (h0i, h0i+1); gates j=0..3 in acc[j]; c in registers.
    const int b0 = mt * 32 + wm * 16 + (lane >> 2);
    const int h0i = (nt * 4 + wn) * 8 + 2 * (lane & 3);
#pragma unroll
    for (int half = 0; half < 2; half++) {
        int b = b0 + half * 8;
        float hn[2];
#pragma unroll
        for (int u = 0; u < 2; u++) {
            int v = half * 2 + u;
            float iv = acc[0][v] + (u ? bi[0].y : bi[0].x);
            float fv = acc[1][v] + (u ? bi[1].y : bi[1].x);
            float gv = acc[2][v] + (u ? bi[2].y : bi[2].x);
            float ov = acc[3][v] + (u ? bi[3].y : bi[3].x);
            float cn = sigf(fv) * creg[v] + sigf(iv) * tanhf(gv);
            creg[v] = cn;
            hn[u] = sigf(ov) * tanhf(cn);
        }
        __nv_bfloat16 h0h, h0l, h1h2, h1l2;
        bsplit(hn[0], h0h, h0l);
        bsplit(hn[1], h1h2, h1l2);
        long hi = (long)b * 512 + h0i;
        *reinterpret_cast<__nv_bfloat162*>(hh + hi) = __nv_bfloat162(h0h, h1h2);
        *reinterpret_cast<__nv_bfloat162*>(hl + hi) = __nv_bfloat162(h0l, h1l2);
        if (hf) *reinterpret_cast<float2*>(hf + hi) = make_float2(hn[0], hn[1]);
    }
}

__global__ __launch_bounds__(256, 1) void decode_loop(
    const float* __restrict__ node, const float* __restrict__ Wo,
    const float* __restrict__ bo, float* __restrict__ out)
{
    extern __shared__ char dsm[];
    uint32_t base = (smem_u32(dsm) + 1023) & ~1023u;
    __shared__ float s_h1[1024];
    __shared__ float s_x[256], s_d[256];
    __shared__ int   s_i[256];

    const int t = threadIdx.x;
    const int bid = blockIdx.x;
    const int mt = bid >> 4, nt = bid & 15;
    const int lane = t & 31, wid = t >> 5;
    const int wn = wid & 3;
    const int q = t >> 7, n = t & 127;

    // preload biases (invariant across steps)
    const int pcb = nt * 128 + wn * 32 + 2 * (lane & 3);
    float2 bi0[4], bi1[4];
#pragma unroll
    for (int j = 0; j < 4; j++) {
        bi0[j] = make_float2(g_bg0[pcb + j * 8], g_bg0[pcb + j * 8 + 1]);
        bi1[j] = make_float2(g_bg1[pcb + j * 8], g_bg1[pcb + j * 8 + 1]);
    }
    float c0reg[4] = {0.f, 0.f, 0.f, 0.f};
    float c1reg[4] = {0.f, 0.f, 0.f, 0.f};

    unsigned* gf = &g_flags[mt][0];
    unsigned bt;
    asm("ld.global.u32 %0, [%1];" : "=r"(bt) : "l"(gf + nt));

    for (int s = 0; s < NNODES; s++) {
        const int cur = s & 1, prev = cur ^ 1;

        // Phase A: gates0 = [dec|h0] @ W0p -> cell0 -> H0[cur]
        gemm_cell_phase(base, g_DECh[prev], g_DECl[prev], 128, 128,
                        g_H0h[prev], g_H0l[prev], 512,
                        g_W0h, g_W0l, 640, bi0, c0reg,
                        g_H0h[cur], g_H0l[cur], nullptr, mt, nt);
        group_sync(gf, nt, ++bt);

        // Phase B: gates1 = [h0_new|h1_prev] @ W1p -> cell1 -> H1[cur] + h1f
        gemm_cell_phase(base, g_H0h[cur], g_H0l[cur], 512, 512,
                        g_H1h[prev], g_H1l[prev], 512,
                        g_W1h, g_W1l, 1024, bi1, c1reg,
                        g_H1h[cur], g_H1l[cur], g_h1f, mt, nt);
        group_sync(gf, nt, ++bt);

        // Tail: projection + masked argmin + scatter + dec feedback (2 batches/CTA)
        {
            const int b = bid * 2 + q;
#pragma unroll
            for (int j = 0; j < 4; j++)
                s_h1[q * 512 + n + j * 128] = g_h1f[(long)b * 512 + n + j * 128];
            __syncthreads();
            float accp = bo[n];
            const float4* wr = reinterpret_cast<const float4*>(Wo + (long)n * 512);
            const float4* hv = reinterpret_cast<const float4*>(s_h1 + q * 512);
#pragma unroll 4
            for (int kq = 0; kq < 128; kq++) {
                float4 w = wr[kq], h4 = hv[kq];
                accp = fmaf(w.x, h4.x, accp); accp = fmaf(w.y, h4.y, accp);
                accp = fmaf(w.z, h4.z, accp); accp = fmaf(w.w, h4.w, accp);
            }
            s_x[q * 128 + n] = accp;
            __syncthreads();
            float dist = 3.4e38f;
            if (!g_used[b * 128 + n]) {
                const float* nd = node + ((long)b * 128 + n) * 128;
                const float* xsb = s_x + q * 128;
                float sum = 0.f;
#pragma unroll 8
                for (int d = 0; d < 128; d++) {
                    float df = xsb[d] - nd[d];
                    sum = fmaf(df, df, sum);
                }
                dist = sum;
            }
            s_d[q * 128 + n] = dist;
            s_i[q * 128 + n] = n;
            __syncthreads();
#pragma unroll
            for (int st_ = 64; st_ > 0; st_ >>= 1) {
                if (n < st_) {
                    float ov = s_d[q * 128 + n + st_]; int oi = s_i[q * 128 + n + st_];
                    if (ov < s_d[q * 128 + n] ||
                        (ov == s_d[q * 128 + n] && oi < s_i[q * 128 + n])) {
                        s_d[q * 128 + n] = ov; s_i[q * 128 + n] = oi;
                    }
                }
                __syncthreads();
            }
            int idx = s_i[q * 128];
            if (n == 0) g_used[b * 128 + idx] = 1;
            float xv = s_x[q * 128 + n];
            out[((long)b * 128 + idx) * 128 + n] = xv;
            __nv_bfloat16 xh, xl;
            bsplit(xv, xh, xl);
            g_DECh[cur][b * 128 + n] = xh;
            g_DECl[cur][b * 128 + n] = xl;
        }
        group_sync(gf, nt, ++bt);
    }
}

// ============================================================================
// Launch
// ============================================================================
extern "C" void kernel_launch(void* const* d_in, const int* in_sizes, int n_in,
                              void* d_out, int out_size)
{
    const float* emb  = (const float*)d_in[0];
    const float* node = (const float*)d_in[1];
    const float* W1   = (const float*)d_in[2];
    const float* b1   = (const float*)d_in[3];
    const float* W2   = (const float*)d_in[4];
    const float* b2   = (const float*)d_in[5];
    const float* Wih0 = (const float*)d_in[6];
    const float* Whh0 = (const float*)d_in[7];
    const float* bih0 = (const float*)d_in[8];
    const float* bhh0 = (const float*)d_in[9];
    const float* Wih1 = (const float*)d_in[10];
    const float* Whh1 = (const float*)d_in[11];
    const float* bih1 = (const float*)d_in[12];
    const float* bhh1 = (const float*)d_in[13];
    const float* Wo   = (const float*)d_in[14];
    const float* bo   = (const float*)d_in[15];
    float* out = (float*)d_out;

    cudaFuncSetAttribute(decode_loop, cudaFuncAttributeMaxDynamicSharedMemorySize, GEMM_SMEM);

    float *pW1ft, *pW2ft, *pt, *phx;
    cudaGetSymbolAddress((void**)&pW1ft, g_W1ft);
    cudaGetSymbolAddress((void**)&pW2ft, g_W2ft);
    cudaGetSymbolAddress((void**)&pt,    g_t);
    cudaGetSymbolAddress((void**)&phx,   g_hx);

    prep_weights<<<2048, 256>>>(Wih0, Whh0, bih0, bhh0, Wih1, Whh1, bih1, bhh1, W1, W2);
    sgemm_bias<<<dim3(512 / TBN, BB / TBM), 256>>>(emb, pW1ft, b1, pt, BB, 512, 512, 512, 1);
    sgemm_bias<<<dim3(1024 / TBN, BB / TBM), 256>>>(pt, pW2ft, b2, phx, BB, 1024, 512, 512, 0);
    init_state<<<(BB * HH) / 256, 256>>>();

    decode_loop<<<NCTA, 256, GEMM_SMEM>>>(node, Wo, bo, out);
}

// round 9
// speedup vs baseline: 1.3980x; 1.2418x over previous
#include <cuda_runtime.h>
#include <cuda_fp16.h>
#include <math.h>
#include <stdint.h>

#define BB 256
#define HH 512
#define NNODES 128
#define NCTA 128

// ============================================================================
// PTX helpers (sm_80+ only — tcgen05 is sm_103a-gated, harness emits compute_103)
// ============================================================================
__device__ __forceinline__ uint32_t smem_u32(const void* p) {
    uint32_t a;
    asm("{ .reg .u64 t; cvta.to.shared.u64 t, %1; cvt.u32.u64 %0, t; }" : "=r"(a) : "l"(p));
    return a;
}
__device__ __forceinline__ void cp16(uint32_t saddr, const void* g) {
    asm volatile("cp.async.cg.shared.global [%0], [%1], 16;" :: "r"(saddr), "l"(g));
}
#define CP_COMMIT() asm volatile("cp.async.commit_group;" ::: "memory")
#define LDSM4(r, a) asm volatile("ldmatrix.sync.aligned.m8n8.x4.shared.b16 {%0,%1,%2,%3}, [%4];" \
    : "=r"((r)[0]), "=r"((r)[1]), "=r"((r)[2]), "=r"((r)[3]) : "r"(a))

__device__ __forceinline__ void mma16816(float* c, const uint32_t* a, const uint32_t* b) {
    asm volatile("mma.sync.aligned.m16n8k16.row.col.f32.f16.f16.f32 "
                 "{%0,%1,%2,%3}, {%4,%5,%6,%7}, {%8,%9}, {%0,%1,%2,%3};"
                 : "+f"(c[0]), "+f"(c[1]), "+f"(c[2]), "+f"(c[3])
                 : "r"(a[0]), "r"(a[1]), "r"(a[2]), "r"(a[3]), "r"(b[0]), "r"(b[1]));
}

// ============================================================================
// Device globals
// ============================================================================
__device__ __align__(16) __half g_W0[2048 * 640];       // single fp16 weights
__device__ __align__(16) __half g_W1[2048 * 1024];
__device__ __align__(16) float g_W1ft[512 * 512], g_W2ft[512 * 1024];
__device__ __align__(16) float g_bg0[2048], g_bg1[2048];
__device__ __align__(16) __half g_H0h[2][BB * HH], g_H0l[2][BB * HH];
__device__ __align__(16) __half g_H1h[2][BB * HH], g_H1l[2][BB * HH];
__device__ __align__(16) __half g_DECh[2][BB * 128], g_DECl[2][BB * 128];
__device__ __align__(16) float g_c0[BB * HH], g_c1[BB * HH], g_h1f[BB * HH];
__device__ __align__(16) float g_t[BB * 512], g_hx[BB * 1024];
__device__ unsigned char g_used[BB * NNODES];

// grid barrier state (zero-initialized at module load; self-consistent across replays)
__device__ unsigned g_cnt;
__device__ volatile unsigned g_gen;

__device__ __forceinline__ void grid_sync() {
    __syncthreads();
    if (threadIdx.x == 0) {
        __threadfence();
        unsigned gen = g_gen;
        if (atomicAdd(&g_cnt, 1u) == NCTA - 1) {
            atomicExch(&g_cnt, 0u);
            __threadfence();
            g_gen = gen + 1;
        } else {
            while (g_gen == gen) { __nanosleep(32); }
        }
        __threadfence();
    }
    __syncthreads();
}

// fp16 hi/lo split: acts are exactly represented as hi + lo (residual ~2^-24)
__device__ __forceinline__ void hsplit(float x, __half& h, __half& l) {
    h = __float2half_rn(x);
    l = __float2half_rn(x - __half2float(h));
}
__device__ __forceinline__ float sigf(float v) { return 1.f / (1.f + expf(-v)); }

// ============================================================================
// Weight prep. Packed column layout: pc = G*32 + gate*8 + u  (G=h/8, u=h%8),
// n_orig = gate*512 + G*8 + u. One warp's 32 cols = all 4 gates of 8 hidden.
// Weights: SINGLE fp16 (no lo part) — halves weight bytes per step.
// ============================================================================
__global__ void prep_weights(const float* __restrict__ Wih0, const float* __restrict__ Whh0,
                             const float* __restrict__ bih0, const float* __restrict__ bhh0,
                             const float* __restrict__ Wih1, const float* __restrict__ Whh1,
                             const float* __restrict__ bih1, const float* __restrict__ bhh1,
                             const float* __restrict__ W1,   const float* __restrict__ W2)
{
    const long S0 = 2048L * 640;
    const long S1 = S0 + 2048L * 1024;
    const long S2 = S1 + 512L * 512;
    const long S3 = S2 + 512L * 1024;
    const long S4 = S3 + 2048;
    const long S5 = S4 + 2048;
    long stride = (long)gridDim.x * blockDim.x;
    for (long i = (long)blockIdx.x * blockDim.x + threadIdx.x; i < S5; i += stride) {
        if (i < S0) {
            long r = i; int pc = (int)(r / 640), k = (int)(r % 640);
            int n = ((pc >> 3) & 3) * 512 + (pc >> 5) * 8 + (pc & 7);
            float w = (k < 128) ? Wih0[(long)n * 128 + k] : Whh0[(long)n * 512 + (k - 128)];
            g_W0[r] = __float2half_rn(w);
        } else if (i < S1) {
            long r = i - S0; int pc = (int)(r / 1024), k = (int)(r % 1024);
            int n = ((pc >> 3) & 3) * 512 + (pc >> 5) * 8 + (pc & 7);
            float w = (k < 512) ? Wih1[(long)n * 512 + k] : Whh1[(long)n * 512 + (k - 512)];
            g_W1[r] = __float2half_rn(w);
        } else if (i < S2) {
            long r = i - S1; int k = (int)(r / 512), j = (int)(r % 512);
            g_W1ft[r] = W1[(long)j * 512 + k];
        } else if (i < S3) {
            long r = i - S2; int k = (int)(r / 1024), j = (int)(r % 1024);
            g_W2ft[r] = W2[(long)j * 512 + k];
        } else if (i < S4) {
            int pc = (int)(i - S3);
            int n = ((pc >> 3) & 3) * 512 + (pc >> 5) * 8 + (pc & 7);
            g_bg0[pc] = bih0[n] + bhh0[n];
        } else {
            int pc = (int)(i - S4);
            int n = ((pc >> 3) & 3) * 512 + (pc >> 5) * 8 + (pc & 7);
            g_bg1[pc] = bih1[n] + bhh1[n];
        }
    }
}

// ============================================================================
// State init (buffers index 1 = "prev" for step 0)
// ============================================================================
__global__ void init_state()
{
    int i = blockIdx.x * blockDim.x + threadIdx.x;
    if (i >= BB * HH) return;
    int b = i >> 9, h = i & 511;
    g_c0[i] = 0.f;
    g_c1[i] = 0.f;
    hsplit(g_hx[b * 1024 + h],       g_H0h[1][i], g_H0l[1][i]);
    hsplit(g_hx[b * 1024 + 512 + h], g_H1h[1][i], g_H1l[1][i]);
    if (h < 128) {
        g_DECh[1][b * 128 + h] = __float2half_rn(0.f);
        g_DECl[1][b * 128 + h] = __float2half_rn(0.f);
        g_used[b * 128 + h] = 0;
    }
}

// ============================================================================
// fp32 SGEMM for the one-time FNN init
// ============================================================================
#define TBM 64
#define TBN 64
#define TBK 16
__global__ __launch_bounds__(256) void sgemm_bias(
    const float* __restrict__ A, const float* __restrict__ Bm,
    const float* __restrict__ bias, float* __restrict__ C,
    int M, int N, int K, int lda, int relu)
{
    __shared__ __align__(16) float As[TBK][TBM + 4];
    __shared__ __align__(16) float Bs[TBK][TBN + 4];
    const int t = threadIdx.x;
    const int bM = blockIdx.y * TBM, bN = blockIdx.x * TBN;
    const int tx = t & 15, ty = t >> 4;
    const int arow = t >> 2, ak = (t & 3) * 4;
    const int bk = t >> 4, bn = (t & 15) * 4;
    float acc[4][4];
#pragma unroll
    for (int i = 0; i < 4; i++)
#pragma unroll
        for (int j = 0; j < 4; j++) acc[i][j] = 0.f;
    for (int k0 = 0; k0 < K; k0 += TBK) {
        float4 a4 = *reinterpret_cast<const float4*>(A + (long)(bM + arow) * lda + k0 + ak);
        As[ak + 0][arow] = a4.x; As[ak + 1][arow] = a4.y;
        As[ak + 2][arow] = a4.z; As[ak + 3][arow] = a4.w;
        *reinterpret_cast<float4*>(&Bs[bk][bn]) =
            *reinterpret_cast<const float4*>(Bm + (long)(k0 + bk) * N + bN + bn);
        __syncthreads();
#pragma unroll
        for (int kk = 0; kk < TBK; kk++) {
            float4 av = *reinterpret_cast<const float4*>(&As[kk][ty * 4]);
            float4 bv = *reinterpret_cast<const float4*>(&Bs[kk][tx * 4]);
            float a[4] = {av.x, av.y, av.z, av.w};
            float b[4] = {bv.x, bv.y, bv.z, bv.w};
#pragma unroll
            for (int i = 0; i < 4; i++)
#pragma unroll
                for (int j = 0; j < 4; j++) acc[i][j] = fmaf(a[i], b[j], acc[i][j]);
        }
        __syncthreads();
    }
    float4 bv = *reinterpret_cast<const float4*>(bias + bN + tx * 4);
    float bb[4] = {bv.x, bv.y, bv.z, bv.w};
#pragma unroll
    for (int i = 0; i < 4; i++) {
        float4 o;
        o.x = acc[i][0] + bb[0]; o.y = acc[i][1] + bb[1];
        o.z = acc[i][2] + bb[2]; o.w = acc[i][3] + bb[3];
        if (relu) { o.x = fmaxf(o.x, 0.f); o.y = fmaxf(o.y, 0.f);
                    o.z = fmaxf(o.z, 0.f); o.w = fmaxf(o.w, 0.f); }
        *reinterpret_cast<float4*>(C + (long)(bM + ty * 4 + i) * N + bN + tx * 4) = o;
    }
}

// ============================================================================
// Persistent decode loop: 128 CTAs x 256 threads (8 warps, warp grid 2x4,
// warp tile 16x32). CTA tile 32(M)x128(N). KC=64 double-buffered cp.async.
// 2-pass fp16 (Ah*B + Al*B), single fp16 weights, LSTM cell in epilogue.
// Structure identical to the 7431us baseline except the precision scheme.
// stage = Ah 4K | Al 4K | B 16K = 24K; x2 = 48K dynamic smem.
// ============================================================================
#define STAGE 24576
#define GEMM_SMEM (2 * STAGE + 1024)

__device__ __forceinline__ void load_a_tile(uint32_t sdst,
    const __half* s1, int str1, int ksplit,
    const __half* s2, int str2, int k0, int mt, int t)
{
    int r = t >> 3;
    int cb = (t & 7) << 4;
    int row = mt * 32 + r;
    const char* src = (k0 < ksplit)
        ? (const char*)(s1 + (long)row * str1 + k0) + cb
        : (const char*)(s2 + (long)row * str2 + (k0 - ksplit)) + cb;
    cp16(sdst + r * 128 + (cb ^ ((r & 7) << 4)), src);
}

__device__ __forceinline__ void load_b_tile(uint32_t sdst, const __half* w,
                                            int K, int k0, int nt, int t)
{
#pragma unroll
    for (int i = 0; i < 4; i++) {
        int idx = i * 256 + t;
        int r = idx >> 3;
        int cb = (idx & 7) << 4;
        cp16(sdst + r * 128 + (cb ^ ((r & 7) << 4)),
             (const char*)(w + (long)(nt * 128 + r) * K + k0) + cb);
    }
}

__device__ __forceinline__ void gemm_cell_phase(uint32_t base,
    const __half* A1h, const __half* A1l, int str1, int ksplit,
    const __half* A2h, const __half* A2l, int str2,
    const __half* W, int K,
    const float* __restrict__ bg,
    float* __restrict__ cst, __half* __restrict__ hh, __half* __restrict__ hl,
    float* __restrict__ hf, int mt, int nt)
{
    const int t = threadIdx.x;
    const int lane = t & 31, wid = t >> 5;
    const int wm = wid >> 2, wn = wid & 3;
    const int nch = K >> 6;

    float acc[4][4];
#pragma unroll
    for (int j = 0; j < 4; j++)
#pragma unroll
        for (int v = 0; v < 4; v++) acc[j][v] = 0.f;

    const int rA = wm * 16 + ((lane >> 3) & 1) * 8 + (lane & 7);
    const int cA = (lane >> 4) * 16;
    const int gB = lane >> 3;
    const int rBb = (gB >> 1) * 8 + (lane & 7);
    const int cB = (gB & 1) * 16;

    // prologue: chunk 0
    {
        load_a_tile(base,        A1h, str1, ksplit, A2h, str2, 0, mt, t);
        load_a_tile(base + 4096, A1l, str1, ksplit, A2l, str2, 0, mt, t);
        load_b_tile(base + 8192, W, K, 0, nt, t);
        CP_COMMIT();
    }

    for (int c = 0; c < nch; c++) {
        if (c + 1 < nch) {
            uint32_t nb = base + ((c + 1) & 1) * STAGE;
            int k0 = (c + 1) * 64;
            load_a_tile(nb,        A1h, str1, ksplit, A2h, str2, k0, mt, t);
            load_a_tile(nb + 4096, A1l, str1, ksplit, A2l, str2, k0, mt, t);
            load_b_tile(nb + 8192, W, K, k0, nt, t);
            CP_COMMIT();
            asm volatile("cp.async.wait_group 1;" ::: "memory");
        } else {
            asm volatile("cp.async.wait_group 0;" ::: "memory");
        }
        __syncthreads();

        uint32_t bb = base + (c & 1) * STAGE;
#pragma unroll
        for (int kk = 0; kk < 4; kk++) {
            uint32_t ah[4], al[4], bh[2][4];
            {
                uint32_t offA = (uint32_t)(rA * 128 + ((kk * 32 + cA) ^ ((rA & 7) << 4)));
                LDSM4(ah, bb + offA);
                LDSM4(al, bb + 4096 + offA);
            }
#pragma unroll
            for (int jj = 0; jj < 2; jj++) {
                int r = wn * 32 + jj * 16 + rBb;
                uint32_t offB = (uint32_t)(r * 128 + ((kk * 32 + cB) ^ ((r & 7) << 4)));
                LDSM4(bh[jj], bb + 8192 + offB);
            }
#pragma unroll
            for (int j = 0; j < 4; j++) {
                const uint32_t* bj = &bh[j >> 1][(j & 1) * 2];
                mma16816(acc[j], ah, bj);   // hi pass
                mma16816(acc[j], al, bj);   // lo pass
            }
        }
        __syncthreads();
    }

    // Epilogue: LSTM cell from fragments. thread owns (b0,b0+8) x (h, h+1),
    // gates j=0..3 in acc[j].
    const int b0 = mt * 32 + wm * 16 + (lane >> 2);
    const int h0i = (nt * 4 + wn) * 8 + 2 * (lane & 3);
    const int pcb = nt * 128 + wn * 32 + 2 * (lane & 3);
    float bi[4][2];
#pragma unroll
    for (int j = 0; j < 4; j++) {
        bi[j][0] = bg[pcb + j * 8];
        bi[j][1] = bg[pcb + j * 8 + 1];
    }
#pragma unroll
    for (int half = 0; half < 2; half++) {
        int b = b0 + half * 8;
        float hn[2];
#pragma unroll
        for (int u = 0; u < 2; u++) {
            int v = half * 2 + u;
            float iv = acc[0][v] + bi[0][u];
            float fv = acc[1][v] + bi[1][u];
            float gv = acc[2][v] + bi[2][u];
            float ov = acc[3][v] + bi[3][u];
            long ci = (long)b * 512 + h0i + u;
            float cn = sigf(fv) * cst[ci] + sigf(iv) * tanhf(gv);
            cst[ci] = cn;
            hn[u] = sigf(ov) * tanhf(cn);
        }
        __half h0h, h0l, h1h2, h1l2;
        hsplit(hn[0], h0h, h0l);
        hsplit(hn[1], h1h2, h1l2);
        long hi = (long)b * 512 + h0i;
        *reinterpret_cast<__half2*>(hh + hi) = __half2(h0h, h1h2);
        *reinterpret_cast<__half2*>(hl + hi) = __half2(h0l, h1l2);
        if (hf) *reinterpret_cast<float2*>(hf + hi) = make_float2(hn[0], hn[1]);
    }
}

__global__ __launch_bounds__(256, 1) void decode_loop(
    const float* __restrict__ node, const float* __restrict__ Wo,
    const float* __restrict__ bo, float* __restrict__ out)
{
    extern __shared__ char dsm[];
    uint32_t base = (smem_u32(dsm) + 1023) & ~1023u;
    __shared__ float s_h1[1024];
    __shared__ float s_x[256], s_d[256];
    __shared__ int   s_i[256];

    const int t = threadIdx.x;
    const int bid = blockIdx.x;
    const int mt = bid >> 4, nt = bid & 15;
    const int q = t >> 7, n = t & 127;   // tail: 2 batches per CTA

    for (int s = 0; s < NNODES; s++) {
        const int cur = s & 1, prev = cur ^ 1;

        // Phase A: gates0 = [dec|h0] @ W0p -> cell0 -> H0[cur]
        gemm_cell_phase(base,
            g_DECh[prev], g_DECl[prev], 128, 128,
            g_H0h[prev],  g_H0l[prev],  512,
            g_W0, 640, g_bg0,
            g_c0, g_H0h[cur], g_H0l[cur], nullptr, mt, nt);
        grid_sync();

        // Phase B: gates1 = [h0_new|h1_prev] @ W1p -> cell1 -> H1[cur] + h1f
        gemm_cell_phase(base,
            g_H0h[cur],  g_H0l[cur],  512, 512,
            g_H1h[prev], g_H1l[prev], 512,
            g_W1, 1024, g_bg1,
            g_c1, g_H1h[cur], g_H1l[cur], g_h1f, mt, nt);
        grid_sync();

        // Tail: projection + masked argmin + scatter + dec feedback
        {
            const int b = bid * 2 + q;
#pragma unroll
            for (int j = 0; j < 4; j++)
                s_h1[q * 512 + n + j * 128] = g_h1f[(long)b * 512 + n + j * 128];
            __syncthreads();
            float accp = bo[n];
            const float4* wr = reinterpret_cast<const float4*>(Wo + (long)n * 512);
            const float4* hv = reinterpret_cast<const float4*>(s_h1 + q * 512);
#pragma unroll 4
            for (int kq = 0; kq < 128; kq++) {
                float4 w = wr[kq], h4 = hv[kq];
                accp = fmaf(w.x, h4.x, accp); accp = fmaf(w.y, h4.y, accp);
                accp = fmaf(w.z, h4.z, accp); accp = fmaf(w.w, h4.w, accp);
            }
            s_x[q * 128 + n] = accp;
            __syncthreads();
            float dist = 3.4e38f;
            if (!g_used[b * 128 + n]) {
                const float* nd = node + ((long)b * 128 + n) * 128;
                const float* xsb = s_x + q * 128;
                float sum = 0.f;
#pragma unroll 8
                for (int d = 0; d < 128; d++) {
                    float df = xsb[d] - nd[d];
                    sum = fmaf(df, df, sum);
                }
                dist = sum;
            }
            s_d[q * 128 + n] = dist;
            s_i[q * 128 + n] = n;
            __syncthreads();
#pragma unroll
            for (int st_ = 64; st_ > 0; st_ >>= 1) {
                if (n < st_) {
                    float ov = s_d[q * 128 + n + st_]; int oi = s_i[q * 128 + n + st_];
                    if (ov < s_d[q * 128 + n] ||
                        (ov == s_d[q * 128 + n] && oi < s_i[q * 128 + n])) {
                        s_d[q * 128 + n] = ov; s_i[q * 128 + n] = oi;
                    }
                }
                __syncthreads();
            }
            int idx = s_i[q * 128];
            if (n == 0) g_used[b * 128 + idx] = 1;
            float xv = s_x[q * 128 + n];
            out[((long)b * 128 + idx) * 128 + n] = xv;
            __half xh, xl;
            hsplit(xv, xh, xl);
            g_DECh[cur][b * 128 + n] = xh;
            g_DECl[cur][b * 128 + n] = xl;
        }
        grid_sync();
    }
}

// ============================================================================
// Launch
// ============================================================================
extern "C" void kernel_launch(void* const* d_in, const int* in_sizes, int n_in,
                              void* d_out, int out_size)
{
    const float* emb  = (const float*)d_in[0];
    const float* node = (const float*)d_in[1];
    const float* W1   = (const float*)d_in[2];
    const float* b1   = (const float*)d_in[3];
    const float* W2   = (const float*)d_in[4];
    const float* b2   = (const float*)d_in[5];
    const float* Wih0 = (const float*)d_in[6];
    const float* Whh0 = (const float*)d_in[7];
    const float* bih0 = (const float*)d_in[8];
    const float* bhh0 = (const float*)d_in[9];
    const float* Wih1 = (const float*)d_in[10];
    const float* Whh1 = (const float*)d_in[11];
    const float* bih1 = (const float*)d_in[12];
    const float* bhh1 = (const float*)d_in[13];
    const float* Wo   = (const float*)d_in[14];
    const float* bo   = (const float*)d_in[15];
    float* out = (float*)d_out;

    cudaFuncSetAttribute(decode_loop, cudaFuncAttributeMaxDynamicSharedMemorySize, GEMM_SMEM);

    float *pW1ft, *pW2ft, *pt, *phx;
    cudaGetSymbolAddress((void**)&pW1ft, g_W1ft);
    cudaGetSymbolAddress((void**)&pW2ft, g_W2ft);
    cudaGetSymbolAddress((void**)&pt,    g_t);
    cudaGetSymbolAddress((void**)&phx,   g_hx);

    prep_weights<<<2048, 256>>>(Wih0, Whh0, bih0, bhh0, Wih1, Whh1, bih1, bhh1, W1, W2);
    sgemm_bias<<<dim3(512 / TBN, BB / TBM), 256>>>(emb, pW1ft, b1, pt, BB, 512, 512, 512, 1);
    sgemm_bias<<<dim3(1024 / TBN, BB / TBM), 256>>>(pt, pW2ft, b2, phx, BB, 1024, 512, 512, 0);
    init_state<<<(BB * HH) / 256, 256>>>();

    decode_loop<<<NCTA, 256, GEMM_SMEM>>>(node, Wo, bo, out);
}

// round 10
// speedup vs baseline: 1.4954x; 1.0697x over previous
#include <cuda_runtime.h>
#include <cuda_fp16.h>
#include <math.h>
#include <stdint.h>

#define BB 256
#define HH 512
#define NNODES 128
#define NCTA 128

// ============================================================================
// PTX helpers (sm_80+ only — tcgen05 is sm_103a-gated, harness emits compute_103)
// ============================================================================
__device__ __forceinline__ uint32_t smem_u32(const void* p) {
    uint32_t a;
    asm("{ .reg .u64 t; cvta.to.shared.u64 t, %1; cvt.u32.u64 %0, t; }" : "=r"(a) : "l"(p));
    return a;
}
__device__ __forceinline__ void cp16(uint32_t saddr, const void* g) {
    asm volatile("cp.async.cg.shared.global [%0], [%1], 16;" :: "r"(saddr), "l"(g));
}
#define CP_COMMIT() asm volatile("cp.async.commit_group;" ::: "memory")
#define LDSM4(r, a) asm volatile("ldmatrix.sync.aligned.m8n8.x4.shared.b16 {%0,%1,%2,%3}, [%4];" \
    : "=r"((r)[0]), "=r"((r)[1]), "=r"((r)[2]), "=r"((r)[3]) : "r"(a))

__device__ __forceinline__ void mma16816(float* c, const uint32_t* a, const uint32_t* b) {
    asm volatile("mma.sync.aligned.m16n8k16.row.col.f32.f16.f16.f32 "
                 "{%0,%1,%2,%3}, {%4,%5,%6,%7}, {%8,%9}, {%0,%1,%2,%3};"
                 : "+f"(c[0]), "+f"(c[1]), "+f"(c[2]), "+f"(c[3])
                 : "r"(a[0]), "r"(a[1]), "r"(a[2]), "r"(a[3]), "r"(b[0]), "r"(b[1]));
}

// ============================================================================
// Device globals
// ============================================================================
__device__ __align__(16) __half g_W0[2048 * 640];       // fp16 weights (packed cols)
__device__ __align__(16) __half g_W1[2048 * 1024];
__device__ __align__(16) float g_W1ft[512 * 512], g_W2ft[512 * 1024];
__device__ __align__(16) float g_bg0[2048], g_bg1[2048];
__device__ __align__(16) __half g_H0[2][BB * HH];       // fp16 activations (single)
__device__ __align__(16) __half g_H1[2][BB * HH];
__device__ __align__(16) __half g_DEC[2][BB * 128];
__device__ __align__(16) float g_c0[BB * HH], g_c1[BB * HH], g_h1f[BB * HH];
__device__ __align__(16) float g_t[BB * 512], g_hx[BB * 1024];
__device__ unsigned char g_used[BB * NNODES];

// grid barrier state (zero-initialized at module load; self-consistent across replays)
__device__ unsigned g_cnt;
__device__ volatile unsigned g_gen;

__device__ __forceinline__ void grid_sync() {
    __syncthreads();
    if (threadIdx.x == 0) {
        __threadfence();
        unsigned gen = g_gen;
        if (atomicAdd(&g_cnt, 1u) == NCTA - 1) {
            atomicExch(&g_cnt, 0u);
            __threadfence();
            g_gen = gen + 1;
        } else {
            while (g_gen == gen) { __nanosleep(32); }
        }
        __threadfence();
    }
    __syncthreads();
}

__device__ __forceinline__ float sigf(float v) { return 1.f / (1.f + expf(-v)); }

// ============================================================================
// Weight prep. Packed column layout: pc = G*32 + gate*8 + u  (G=h/8, u=h%8),
// n_orig = gate*512 + G*8 + u. One warp's 32 cols = all 4 gates of 8 hidden.
// ============================================================================
__global__ void prep_weights(const float* __restrict__ Wih0, const float* __restrict__ Whh0,
                             const float* __restrict__ bih0, const float* __restrict__ bhh0,
                             const float* __restrict__ Wih1, const float* __restrict__ Whh1,
                             const float* __restrict__ bih1, const float* __restrict__ bhh1,
                             const float* __restrict__ W1,   const float* __restrict__ W2)
{
    const long S0 = 2048L * 640;
    const long S1 = S0 + 2048L * 1024;
    const long S2 = S1 + 512L * 512;
    const long S3 = S2 + 512L * 1024;
    const long S4 = S3 + 2048;
    const long S5 = S4 + 2048;
    long stride = (long)gridDim.x * blockDim.x;
    for (long i = (long)blockIdx.x * blockDim.x + threadIdx.x; i < S5; i += stride) {
        if (i < S0) {
            long r = i; int pc = (int)(r / 640), k = (int)(r % 640);
            int n = ((pc >> 3) & 3) * 512 + (pc >> 5) * 8 + (pc & 7);
            float w = (k < 128) ? Wih0[(long)n * 128 + k] : Whh0[(long)n * 512 + (k - 128)];
            g_W0[r] = __float2half_rn(w);
        } else if (i < S1) {
            long r = i - S0; int pc = (int)(r / 1024), k = (int)(r % 1024);
            int n = ((pc >> 3) & 3) * 512 + (pc >> 5) * 8 + (pc & 7);
            float w = (k < 512) ? Wih1[(long)n * 512 + k] : Whh1[(long)n * 512 + (k - 512)];
            g_W1[r] = __float2half_rn(w);
        } else if (i < S2) {
            long r = i - S1; int k = (int)(r / 512), j = (int)(r % 512);
            g_W1ft[r] = W1[(long)j * 512 + k];
        } else if (i < S3) {
            long r = i - S2; int k = (int)(r / 1024), j = (int)(r % 1024);
            g_W2ft[r] = W2[(long)j * 512 + k];
        } else if (i < S4) {
            int pc = (int)(i - S3);
            int n = ((pc >> 3) & 3) * 512 + (pc >> 5) * 8 + (pc & 7);
            g_bg0[pc] = bih0[n] + bhh0[n];
        } else {
            int pc = (int)(i - S4);
            int n = ((pc >> 3) & 3) * 512 + (pc >> 5) * 8 + (pc & 7);
            g_bg1[pc] = bih1[n] + bhh1[n];
        }
    }
}

// ============================================================================
// State init (buffers index 1 = "prev" for step 0)
// ============================================================================
__global__ void init_state()
{
    int i = blockIdx.x * blockDim.x + threadIdx.x;
    if (i >= BB * HH) return;
    int b = i >> 9, h = i & 511;
    g_c0[i] = 0.f;
    g_c1[i] = 0.f;
    g_H0[1][i] = __float2half_rn(g_hx[b * 1024 + h]);
    g_H1[1][i] = __float2half_rn(g_hx[b * 1024 + 512 + h]);
    if (h < 128) {
        g_DEC[1][b * 128 + h] = __float2half_rn(0.f);
        g_used[b * 128 + h] = 0;
    }
}

// ============================================================================
// fp32 SGEMM for the one-time FNN init
// ============================================================================
#define TBM 64
#define TBN 64
#define TBK 16
__global__ __launch_bounds__(256) void sgemm_bias(
    const float* __restrict__ A, const float* __restrict__ Bm,
    const float* __restrict__ bias, float* __restrict__ C,
    int M, int N, int K, int lda, int relu)
{
    __shared__ __align__(16) float As[TBK][TBM + 4];
    __shared__ __align__(16) float Bs[TBK][TBN + 4];
    const int t = threadIdx.x;
    const int bM = blockIdx.y * TBM, bN = blockIdx.x * TBN;
    const int tx = t & 15, ty = t >> 4;
    const int arow = t >> 2, ak = (t & 3) * 4;
    const int bk = t >> 4, bn = (t & 15) * 4;
    float acc[4][4];
#pragma unroll
    for (int i = 0; i < 4; i++)
#pragma unroll
        for (int j = 0; j < 4; j++) acc[i][j] = 0.f;
    for (int k0 = 0; k0 < K; k0 += TBK) {
        float4 a4 = *reinterpret_cast<const float4*>(A + (long)(bM + arow) * lda + k0 + ak);
        As[ak + 0][arow] = a4.x; As[ak + 1][arow] = a4.y;
        As[ak + 2][arow] = a4.z; As[ak + 3][arow] = a4.w;
        *reinterpret_cast<float4*>(&Bs[bk][bn]) =
            *reinterpret_cast<const float4*>(Bm + (long)(k0 + bk) * N + bN + bn);
        __syncthreads();
#pragma unroll
        for (int kk = 0; kk < TBK; kk++) {
            float4 av = *reinterpret_cast<const float4*>(&As[kk][ty * 4]);
            float4 bv = *reinterpret_cast<const float4*>(&Bs[kk][tx * 4]);
            float a[4] = {av.x, av.y, av.z, av.w};
            float b[4] = {bv.x, bv.y, bv.z, bv.w};
#pragma unroll
            for (int i = 0; i < 4; i++)
#pragma unroll
                for (int j = 0; j < 4; j++) acc[i][j] = fmaf(a[i], b[j], acc[i][j]);
        }
        __syncthreads();
    }
    float4 bv = *reinterpret_cast<const float4*>(bias + bN + tx * 4);
    float bb[4] = {bv.x, bv.y, bv.z, bv.w};
#pragma unroll
    for (int i = 0; i < 4; i++) {
        float4 o;
        o.x = acc[i][0] + bb[0]; o.y = acc[i][1] + bb[1];
        o.z = acc[i][2] + bb[2]; o.w = acc[i][3] + bb[3];
        if (relu) { o.x = fmaxf(o.x, 0.f); o.y = fmaxf(o.y, 0.f);
                    o.z = fmaxf(o.z, 0.f); o.w = fmaxf(o.w, 0.f); }
        *reinterpret_cast<float4*>(C + (long)(bM + ty * 4 + i) * N + bN + tx * 4) = o;
    }
}

// ============================================================================
// Persistent decode loop: 128 CTAs x 256 threads (8 warps, warp grid 2x4,
// warp tile 16x32). CTA tile 32(M)x128(N). KC=64 double-buffered cp.async.
// SINGLE-pass pure fp16 GEMM (4 HMMA per kk), LSTM cell in epilogue.
// Structure identical to the 6638us kernel except the lo-pass is removed.
// stage = A 4K | B 16K = 20K; x2 = 40K dynamic smem.
// ============================================================================
#define STAGE 20480
#define GEMM_SMEM (2 * STAGE + 1024)

__device__ __forceinline__ void load_a_tile(uint32_t sdst,
    const __half* s1, int str1, int ksplit,
    const __half* s2, int str2, int k0, int mt, int t)
{
    int r = t >> 3;
    int cb = (t & 7) << 4;
    int row = mt * 32 + r;
    const char* src = (k0 < ksplit)
        ? (const char*)(s1 + (long)row * str1 + k0) + cb
        : (const char*)(s2 + (long)row * str2 + (k0 - ksplit)) + cb;
    cp16(sdst + r * 128 + (cb ^ ((r & 7) << 4)), src);
}

__device__ __forceinline__ void load_b_tile(uint32_t sdst, const __half* w,
                                            int K, int k0, int nt, int t)
{
#pragma unroll
    for (int i = 0; i < 4; i++) {
        int idx = i * 256 + t;
        int r = idx >> 3;
        int cb = (idx & 7) << 4;
        cp16(sdst + r * 128 + (cb ^ ((r & 7) << 4)),
             (const char*)(w + (long)(nt * 128 + r) * K + k0) + cb);
    }
}

__device__ __forceinline__ void gemm_cell_phase(uint32_t base,
    const __half* A1, int str1, int ksplit,
    const __half* A2, int str2,
    const __half* W, int K,
    const float* __restrict__ bg,
    float* __restrict__ cst, __half* __restrict__ hh,
    float* __restrict__ hf, int mt, int nt)
{
    const int t = threadIdx.x;
    const int lane = t & 31, wid = t >> 5;
    const int wm = wid >> 2, wn = wid & 3;
    const int nch = K >> 6;

    float acc[4][4];
#pragma unroll
    for (int j = 0; j < 4; j++)
#pragma unroll
        for (int v = 0; v < 4; v++) acc[j][v] = 0.f;

    const int rA = wm * 16 + ((lane >> 3) & 1) * 8 + (lane & 7);
    const int cA = (lane >> 4) * 16;
    const int gB = lane >> 3;
    const int rBb = (gB >> 1) * 8 + (lane & 7);
    const int cB = (gB & 1) * 16;

    // prologue: chunk 0
    {
        load_a_tile(base, A1, str1, ksplit, A2, str2, 0, mt, t);
        load_b_tile(base + 4096, W, K, 0, nt, t);
        CP_COMMIT();
    }

    for (int c = 0; c < nch; c++) {
        if (c + 1 < nch) {
            uint32_t nb = base + ((c + 1) & 1) * STAGE;
            int k0 = (c + 1) * 64;
            load_a_tile(nb, A1, str1, ksplit, A2, str2, k0, mt, t);
            load_b_tile(nb + 4096, W, K, k0, nt, t);
            CP_COMMIT();
            asm volatile("cp.async.wait_group 1;" ::: "memory");
        } else {
            asm volatile("cp.async.wait_group 0;" ::: "memory");
        }
        __syncthreads();

        uint32_t bb = base + (c & 1) * STAGE;
#pragma unroll
        for (int kk = 0; kk < 4; kk++) {
            uint32_t ah[4], bh[2][4];
            {
                uint32_t offA = (uint32_t)(rA * 128 + ((kk * 32 + cA) ^ ((rA & 7) << 4)));
                LDSM4(ah, bb + offA);
            }
#pragma unroll
            for (int jj = 0; jj < 2; jj++) {
                int r = wn * 32 + jj * 16 + rBb;
                uint32_t offB = (uint32_t)(r * 128 + ((kk * 32 + cB) ^ ((r & 7) << 4)));
                LDSM4(bh[jj], bb + 4096 + offB);
            }
#pragma unroll
            for (int j = 0; j < 4; j++) {
                const uint32_t* bj = &bh[j >> 1][(j & 1) * 2];
                mma16816(acc[j], ah, bj);
            }
        }
        __syncthreads();
    }

    // Epilogue: LSTM cell from fragments. thread owns (b0,b0+8) x (h, h+1),
    // gates j=0..3 in acc[j].
    const int b0 = mt * 32 + wm * 16 + (lane >> 2);
    const int h0i = (nt * 4 + wn) * 8 + 2 * (lane & 3);
    const int pcb = nt * 128 + wn * 32 + 2 * (lane & 3);
    float bi[4][2];
#pragma unroll
    for (int j = 0; j < 4; j++) {
        bi[j][0] = bg[pcb + j * 8];
        bi[j][1] = bg[pcb + j * 8 + 1];
    }
#pragma unroll
    for (int half = 0; half < 2; half++) {
        int b = b0 + half * 8;
        float hn[2];
#pragma unroll
        for (int u = 0; u < 2; u++) {
            int v = half * 2 + u;
            float iv = acc[0][v] + bi[0][u];
            float fv = acc[1][v] + bi[1][u];
            float gv = acc[2][v] + bi[2][u];
            float ov = acc[3][v] + bi[3][u];
            long ci = (long)b * 512 + h0i + u;
            float cn = sigf(fv) * cst[ci] + sigf(iv) * tanhf(gv);
            cst[ci] = cn;
            hn[u] = sigf(ov) * tanhf(cn);
        }
        long hi = (long)b * 512 + h0i;
        *reinterpret_cast<__half2*>(hh + hi) =
            __half2(__float2half_rn(hn[0]), __float2half_rn(hn[1]));
        if (hf) *reinterpret_cast<float2*>(hf + hi) = make_float2(hn[0], hn[1]);
    }
}

__global__ __launch_bounds__(256, 1) void decode_loop(
    const float* __restrict__ node, const float* __restrict__ Wo,
    const float* __restrict__ bo, float* __restrict__ out)
{
    extern __shared__ char dsm[];
    uint32_t base = (smem_u32(dsm) + 1023) & ~1023u;
    __shared__ float s_h1[1024];
    __shared__ float s_x[256], s_d[256];
    __shared__ int   s_i[256];

    const int t = threadIdx.x;
    const int bid = blockIdx.x;
    const int mt = bid >> 4, nt = bid & 15;
    const int q = t >> 7, n = t & 127;   // tail: 2 batches per CTA

    for (int s = 0; s < NNODES; s++) {
        const int cur = s & 1, prev = cur ^ 1;

        // Phase A: gates0 = [dec|h0] @ W0p -> cell0 -> H0[cur]
        gemm_cell_phase(base,
            g_DEC[prev], 128, 128,
            g_H0[prev],  512,
            g_W0, 640, g_bg0,
            g_c0, g_H0[cur], nullptr, mt, nt);
        grid_sync();

        // Phase B: gates1 = [h0_new|h1_prev] @ W1p -> cell1 -> H1[cur] + h1f
        gemm_cell_phase(base,
            g_H0[cur], 512, 512,
            g_H1[prev], 512,
            g_W1, 1024, g_bg1,
            g_c1, g_H1[cur], g_h1f, mt, nt);
        grid_sync();

        // Tail: projection + masked argmin + scatter + dec feedback
        {
            const int b = bid * 2 + q;
#pragma unroll
            for (int j = 0; j < 4; j++)
                s_h1[q * 512 + n + j * 128] = g_h1f[(long)b * 512 + n + j * 128];
            __syncthreads();
            float accp = bo[n];
            const float4* wr = reinterpret_cast<const float4*>(Wo + (long)n * 512);
            const float4* hv = reinterpret_cast<const float4*>(s_h1 + q * 512);
#pragma unroll 4
            for (int kq = 0; kq < 128; kq++) {
                float4 w = wr[kq], h4 = hv[kq];
                accp = fmaf(w.x, h4.x, accp); accp = fmaf(w.y, h4.y, accp);
                accp = fmaf(w.z, h4.z, accp); accp = fmaf(w.w, h4.w, accp);
            }
            s_x[q * 128 + n] = accp;
            __syncthreads();
            float dist = 3.4e38f;
            if (!g_used[b * 128 + n]) {
                const float* nd = node + ((long)b * 128 + n) * 128;
                const float* xsb = s_x + q * 128;
                float sum = 0.f;
#pragma unroll 8
                for (int d = 0; d < 128; d++) {
                    float df = xsb[d] - nd[d];
                    sum = fmaf(df, df, sum);
                }
                dist = sum;
            }
            s_d[q * 128 + n] = dist;
            s_i[q * 128 + n] = n;
            __syncthreads();
#pragma unroll
            for (int st_ = 64; st_ > 0; st_ >>= 1) {
                if (n < st_) {
                    float ov = s_d[q * 128 + n + st_]; int oi = s_i[q * 128 + n + st_];
                    if (ov < s_d[q * 128 + n] ||
                        (ov == s_d[q * 128 + n] && oi < s_i[q * 128 + n])) {
                        s_d[q * 128 + n] = ov; s_i[q * 128 + n] = oi;
                    }
                }
                __syncthreads();
            }
            int idx = s_i[q * 128];
            if (n == 0) g_used[b * 128 + idx] = 1;
            float xv = s_x[q * 128 + n];
            out[((long)b * 128 + idx) * 128 + n] = xv;
            g_DEC[cur][b * 128 + n] = __float2half_rn(xv);
        }
        grid_sync();
    }
}

// ============================================================================
// Launch
// ============================================================================
extern "C" void kernel_launch(void* const* d_in, const int* in_sizes, int n_in,
                              void* d_out, int out_size)
{
    const float* emb  = (const float*)d_in[0];
    const float* node = (const float*)d_in[1];
    const float* W1   = (const float*)d_in[2];
    const float* b1   = (const float*)d_in[3];
    const float* W2   = (const float*)d_in[4];
    const float* b2   = (const float*)d_in[5];
    const float* Wih0 = (const float*)d_in[6];
    const float* Whh0 = (const float*)d_in[7];
    const float* bih0 = (const float*)d_in[8];
    const float* bhh0 = (const float*)d_in[9];
    const float* Wih1 = (const float*)d_in[10];
    const float* Whh1 = (const float*)d_in[11];
    const float* bih1 = (const float*)d_in[12];
    const float* bhh1 = (const float*)d_in[13];
    const float* Wo   = (const float*)d_in[14];
    const float* bo   = (const float*)d_in[15];
    float* out = (float*)d_out;

    cudaFuncSetAttribute(decode_loop, cudaFuncAttributeMaxDynamicSharedMemorySize, GEMM_SMEM);

    float *pW1ft, *pW2ft, *pt, *phx;
    cudaGetSymbolAddress((void**)&pW1ft, g_W1ft);
    cudaGetSymbolAddress((void**)&pW2ft, g_W2ft);
    cudaGetSymbolAddress((void**)&pt,    g_t);
    cudaGetSymbolAddress((void**)&phx,   g_hx);

    prep_weights<<<2048, 256>>>(Wih0, Whh0, bih0, bhh0, Wih1, Whh1, bih1, bhh1, W1, W2);
    sgemm_bias<<<dim3(512 / TBN, BB / TBM), 256>>>(emb, pW1ft, b1, pt, BB, 512, 512, 512, 1);
    sgemm_bias<<<dim3(1024 / TBN, BB / TBM), 256>>>(pt, pW2ft, b2, phx, BB, 1024, 512, 512, 0);
    init_state<<<(BB * HH) / 256, 256>>>();

    decode_loop<<<NCTA, 256, GEMM_SMEM>>>(node, Wo, bo, out);
}